// round 1
// baseline (speedup 1.0000x reference)
#include <cuda_runtime.h>
#include <cstdint>
#include <cstdio>

// GRUModel: y = GRUCell(x, hid) applied independently per (t, b).
//   gi = x @ W_ih^T + b_ih ; gh = hid @ W_hh^T + b_hh
//   r = sigmoid(gi_r + gh_r); z = sigmoid(gi_z + gh_z)
//   n = tanh(gi_n + r * gh_n); y = (1-z)*n + z*hid
// Outputs: concat(y, hid)  -> out_size = 2*T*B*H floats.
//
// Strategy: fused tf32 mma.sync kernel. M = T*B = 131072 rows, K = 128,
// 6 sub-GEMMs (3 gates x 2 weight mats) of shape [64 x 64 x 128] per block,
// epilogue entirely in registers. hid tile kept whole in smem -> second
// output (hid copy) written from smem for free.

#define T_ 512
#define B_ 256
#define H_ 128
#define K_ 128
#define M_ (T_ * B_)        // 131072
#define BM 64
#define BH 64
#define NTHREADS 512
#define XS_STRIDE 132       // 128 + 4 pad: conflict-free frag loads
#define WS_STRIDE 9         // 8 + 1 pad
#define WS_TILE (BM * WS_STRIDE)  // 576 floats per (buf, j)

__device__ __forceinline__ uint32_t f2tf(float f) {
    uint32_t u;
    asm("cvt.rna.tf32.f32 %0, %1;" : "=r"(u) : "f"(f));
    return u;
}

__device__ __forceinline__ void mma_tf32(float* c, const uint32_t* a, const uint32_t* b) {
    asm volatile(
        "mma.sync.aligned.m16n8k8.row.col.f32.tf32.tf32.f32 "
        "{%0,%1,%2,%3}, {%4,%5,%6,%7}, {%8,%9}, {%0,%1,%2,%3};"
        : "+f"(c[0]), "+f"(c[1]), "+f"(c[2]), "+f"(c[3])
        : "r"(a[0]), "r"(a[1]), "r"(a[2]), "r"(a[3]),
          "r"(b[0]), "r"(b[1]));
}

__global__ void __launch_bounds__(NTHREADS, 1)
gru_fused_kernel(const float* __restrict__ x,
                 const float* __restrict__ hid,
                 const float* __restrict__ W_ih,
                 const float* __restrict__ W_hh,
                 const float* __restrict__ b_ih,
                 const float* __restrict__ b_hh,
                 float* __restrict__ out)
{
    extern __shared__ float smem[];
    float* xs = smem;                       // [BM][XS_STRIDE]
    float* hs = smem + BM * XS_STRIDE;      // [BM][XS_STRIDE]
    float* ws = hs + BM * XS_STRIDE;        // [2][6][WS_TILE]

    const int tid  = threadIdx.x;
    const int warp = tid >> 5;
    const int lane = tid & 31;
    const int wm = warp >> 2;       // 0..3  warp row (16 m each)
    const int wh = warp & 3;        // 0..3  warp col (16 h each)
    const int g  = lane >> 2;       // 0..7
    const int c  = lane & 3;        // 0..3

    const int bm = blockIdx.x * BM;
    const int h0 = blockIdx.y * BH;

    // ---- load x, hid tiles [BM x 128] via float4 (fully coalesced) ----
    {
        const float4* xg = (const float4*)(x   + (size_t)bm * K_);
        const float4* hg = (const float4*)(hid + (size_t)bm * K_);
        #pragma unroll
        for (int i = 0; i < 4; i++) {
            int idx = i * NTHREADS + tid;   // 0..2047
            int row = idx >> 5;             // 32 float4 per row
            int col = idx & 31;
            float4 vx = xg[row * 32 + col];
            float4 vh = hg[row * 32 + col];
            *(float4*)(xs + row * XS_STRIDE + col * 4) = vx;
            *(float4*)(hs + row * XS_STRIDE + col * 4) = vh;
        }
    }

    // ---- preload W k-chunk 0 into ws buffer 0 ----
    // layout: ws[buf][j][h * WS_STRIDE + kk], j in 0..2 -> W_ih gates, 3..5 -> W_hh
    {
        int hh = tid >> 3, kk = tid & 7;
        #pragma unroll
        for (int j = 0; j < 6; j++) {
            const float* W = (j < 3) ? W_ih : W_hh;
            int gr = (j % 3) * H_ + h0 + hh;          // global weight row
            ws[j * WS_TILE + hh * WS_STRIDE + kk] = W[gr * K_ + kk];
        }
    }
    __syncthreads();

    float acc[6][2][4];
    #pragma unroll
    for (int j = 0; j < 6; j++)
        #pragma unroll
        for (int n = 0; n < 2; n++)
            #pragma unroll
            for (int e = 0; e < 4; e++) acc[j][n][e] = 0.f;

    const int NKC = K_ / 8;   // 16 k-chunks
    for (int kc = 0; kc < NKC; kc++) {
        const int cur = kc & 1;
        const int nxt = cur ^ 1;

        // prefetch next W k-chunk (L2-hot, tiny)
        if (kc + 1 < NKC) {
            int hh = tid >> 3, kk = tid & 7;
            #pragma unroll
            for (int j = 0; j < 6; j++) {
                const float* W = (j < 3) ? W_ih : W_hh;
                int gr = (j % 3) * H_ + h0 + hh;
                ws[(nxt * 6 + j) * WS_TILE + hh * WS_STRIDE + kk] =
                    W[gr * K_ + (kc + 1) * 8 + kk];
            }
        }

        // A fragments (x and hid), m16k8, row-major
        uint32_t ax[4], ah[4];
        {
            int r0 = wm * 16 + g, r1 = r0 + 8;
            int k0 = kc * 8 + c,  k1 = k0 + 4;
            ax[0] = f2tf(xs[r0 * XS_STRIDE + k0]);
            ax[1] = f2tf(xs[r1 * XS_STRIDE + k0]);
            ax[2] = f2tf(xs[r0 * XS_STRIDE + k1]);
            ax[3] = f2tf(xs[r1 * XS_STRIDE + k1]);
            ah[0] = f2tf(hs[r0 * XS_STRIDE + k0]);
            ah[1] = f2tf(hs[r1 * XS_STRIDE + k0]);
            ah[2] = f2tf(hs[r0 * XS_STRIDE + k1]);
            ah[3] = f2tf(hs[r1 * XS_STRIDE + k1]);
        }

        #pragma unroll
        for (int j = 0; j < 6; j++) {
            const float* wsj = ws + (cur * 6 + j) * WS_TILE;
            const uint32_t* A = (j < 3) ? ax : ah;
            #pragma unroll
            for (int nt = 0; nt < 2; nt++) {
                int hn = wh * 16 + nt * 8 + g;   // B col (= weight row) for this lane
                uint32_t b[2];
                b[0] = f2tf(wsj[hn * WS_STRIDE + c]);
                b[1] = f2tf(wsj[hn * WS_STRIDE + c + 4]);
                mma_tf32(acc[j][nt], A, b);
            }
        }
        __syncthreads();
    }

    // ---- epilogue: gates + both outputs ----
    const size_t TBH = (size_t)M_ * H_;
    #pragma unroll
    for (int nt = 0; nt < 2; nt++) {
        #pragma unroll
        for (int rr = 0; rr < 2; rr++) {
            #pragma unroll
            for (int cc = 0; cc < 2; cc++) {
                int e  = rr * 2 + cc;                  // C frag element
                int ml = wm * 16 + g + rr * 8;         // local m
                int hl = wh * 16 + nt * 8 + 2 * c + cc;// local h
                int m = bm + ml;
                int h = h0 + hl;

                float gir = acc[0][nt][e] + __ldg(&b_ih[h]);
                float giz = acc[1][nt][e] + __ldg(&b_ih[h + H_]);
                float gin = acc[2][nt][e] + __ldg(&b_ih[h + 2 * H_]);
                float ghr = acc[3][nt][e] + __ldg(&b_hh[h]);
                float ghz = acc[4][nt][e] + __ldg(&b_hh[h + H_]);
                float ghn = acc[5][nt][e] + __ldg(&b_hh[h + 2 * H_]);

                float r = 1.f / (1.f + __expf(-(gir + ghr)));
                float z = 1.f / (1.f + __expf(-(giz + ghz)));
                float n = tanhf(gin + r * ghn);
                float hv = hs[ml * XS_STRIDE + h];   // hid[m][h] from smem tile
                float y = (1.f - z) * n + z * hv;

                out[(size_t)m * H_ + h] = y;
                out[TBH + (size_t)m * H_ + h] = hv;  // second output: hid copy
            }
        }
    }
}

extern "C" void kernel_launch(void* const* d_in, const int* in_sizes, int n_in,
                              void* d_out, int out_size) {
    (void)in_sizes; (void)n_in; (void)out_size;
    const float* x    = (const float*)d_in[0];
    const float* hid  = (const float*)d_in[1];
    const float* W_ih = (const float*)d_in[2];
    const float* W_hh = (const float*)d_in[3];
    const float* b_ih = (const float*)d_in[4];
    const float* b_hh = (const float*)d_in[5];
    float* out = (float*)d_out;

    const int smem_bytes = (2 * BM * XS_STRIDE + 2 * 6 * WS_TILE) * (int)sizeof(float);
    cudaFuncSetAttribute(gru_fused_kernel,
                         cudaFuncAttributeMaxDynamicSharedMemorySize, smem_bytes);

    dim3 grid(M_ / BM, H_ / BH);   // (2048, 2)
    gru_fused_kernel<<<grid, NTHREADS, smem_bytes>>>(x, hid, W_ih, W_hh,
                                                     b_ih, b_hh, out);
}

// round 5
// speedup vs baseline: 1.9331x; 1.9331x over previous
#include <cuda_runtime.h>
#include <cstdint>

// ============================================================================
// GRU per-timestep cell, batched: M = T*B = 131072, K = 128, H = 128.
//   s_r = x@Wih_r^T + hid@Whh_r^T ; s_z likewise ; gi_n = x@Wih_n^T ; gh_n = hid@Whh_n^T
//   r = sig(s_r + br), z = sig(s_z + bz), n = tanh(gi_n + bin + r*(gh_n + bhn))
//   y = (1-z)*n + z*hid ; out = concat(y, hid)
//
// tf32 mma.sync (m16n8k8), compute_103-safe (no tcgen05 -- gated by harness PTX arch).
//   - prep kernel converts weights to tf32 scratch in fragment-pair layout
//     (one LDS.64 per B fragment, zero CVT in mainloop)
//   - 512 thr/block, block tile 128m x 64h, warp tile 32m x 16h (B frags reused 2x)
//   - 4 accumulator panels (r,z merged across ih/hh inside the MMA stream)
//   - cp.async 4-stage weight pipeline; block loops over both h-halves
// ============================================================================

#define T_ 512
#define B_ 256
#define H_ 128
#define K_ 128
#define M_ (T_ * B_)            // 131072
#define BM 128
#define NTHREADS 512
#define XS_STRIDE 132           // 128 + 4 words pad: conflict-free frag loads
#define W_SLICE_WORDS 3072      // 6 mats * 64 h * 8 k (pair layout) per stage
#define NSTAGES 32              // 2 hblk * 16 kc

// weight scratch: [hblk][kc][j][h][c][p]  (tf32 bits)
__device__ uint32_t g_wscr[2 * 16 * 6 * 64 * 8];   // 98304 words = 384 KB

__device__ __forceinline__ uint32_t f2tf(float f) {
    uint32_t u;
    asm("cvt.rna.tf32.f32 %0, %1;" : "=r"(u) : "f"(f));
    return u;
}

__device__ __forceinline__ void mma_tf32(float* c, const uint32_t* a, const uint32_t* b) {
    asm volatile(
        "mma.sync.aligned.m16n8k8.row.col.f32.tf32.tf32.f32 "
        "{%0,%1,%2,%3}, {%4,%5,%6,%7}, {%8,%9}, {%0,%1,%2,%3};"
        : "+f"(c[0]), "+f"(c[1]), "+f"(c[2]), "+f"(c[3])
        : "r"(a[0]), "r"(a[1]), "r"(a[2]), "r"(a[3]),
          "r"(b[0]), "r"(b[1]));
}

__device__ __forceinline__ uint32_t smem_u32(const void* p) {
    uint32_t a;
    asm("{ .reg .u64 t; cvta.to.shared.u64 t, %1; cvt.u32.u64 %0, t; }"
        : "=r"(a) : "l"(p));
    return a;
}

__device__ __forceinline__ float sigmoidf_(float x) {
    return 1.0f / (1.0f + __expf(-x));
}
__device__ __forceinline__ float tanhf_(float x) {
    float e = __expf(2.0f * x);          // saturates correctly at +-inf
    return 1.0f - 2.0f / (e + 1.0f);
}

// ---------------------------------------------------------------------------
// Prep: scatter W_ih/W_hh into tf32 fragment-pair layout.
//   idx = ((((hblk*16 + kc)*6 + j)*64 + h)*4 + c)*2 + p
//   value = W[(j%3)*128 + hblk*64 + h][kc*8 + c + p*4]
// ---------------------------------------------------------------------------
__global__ void gru_prep_w(const float* __restrict__ W_ih,
                           const float* __restrict__ W_hh) {
    int idx = blockIdx.x * 256 + threadIdx.x;        // 0..98303
    int p = idx & 1;
    int c = (idx >> 1) & 3;
    int h = (idx >> 3) & 63;
    int rest = idx >> 9;
    int j = rest % 6;
    int rest2 = rest / 6;
    int kc = rest2 & 15;
    int hblk = rest2 >> 4;
    int k = kc * 8 + c + p * 4;
    int row = (j % 3) * H_ + hblk * 64 + h;
    const float* W = (j < 3) ? W_ih : W_hh;
    g_wscr[idx] = f2tf(W[row * K_ + k]);
}

// ---------------------------------------------------------------------------
// Main fused kernel
// ---------------------------------------------------------------------------
__global__ void __launch_bounds__(NTHREADS, 1)
gru_main(const float* __restrict__ x,
         const float* __restrict__ hid,
         const float* __restrict__ b_ih,
         const float* __restrict__ b_hh,
         float* __restrict__ out)
{
    extern __shared__ char smem[];
    uint32_t* xs = (uint32_t*)smem;                  // [128][XS_STRIDE]
    uint32_t* hs = xs + BM * XS_STRIDE;
    uint32_t* ws = hs + BM * XS_STRIDE;              // [4][W_SLICE_WORDS]
    float*  bias = (float*)(ws + 4 * W_SLICE_WORDS); // br/bz/bin/bhn: 4 x 64

    const int tid  = threadIdx.x;
    const int warp = tid >> 5;
    const int lane = tid & 31;
    const int wm   = warp & 3;        // 0..3: 32-row slab
    const int wh   = warp >> 2;       // 0..3: 16-col slab
    const int g    = lane >> 2;       // 0..7
    const int c    = lane & 3;        // 0..3
    const int bm   = blockIdx.x * BM;

    const uint32_t ws_sa = smem_u32(ws);

    // ---- weight pipeline prologue: stages 0..2 ---------------------------
    #pragma unroll
    for (int s = 0; s < 3; s++) {
        const uint4* src = (const uint4*)(g_wscr + (size_t)s * W_SLICE_WORDS);
        uint32_t dst = ws_sa + (uint32_t)(s & 3) * (W_SLICE_WORDS * 4);
        for (int i = tid; i < 768; i += NTHREADS) {
            asm volatile("cp.async.ca.shared.global [%0], [%1], 16;"
                         :: "r"(dst + i * 16), "l"(src + i) : "memory");
        }
        asm volatile("cp.async.commit_group;" ::: "memory");
    }

    // ---- load + convert x/hid tiles [128 x 128] --------------------------
    {
        const float4* xg = (const float4*)(x   + (size_t)bm * K_);
        const float4* hg = (const float4*)(hid + (size_t)bm * K_);
        #pragma unroll
        for (int i = 0; i < 8; i++) {
            int idx  = i * NTHREADS + tid;       // 0..4095
            int row  = idx >> 5;                 // 32 float4 per row
            int col4 = idx & 31;
            float4 vx = xg[row * 32 + col4];
            float4 vh = hg[row * 32 + col4];
            uint4 ux, uh;
            ux.x = f2tf(vx.x); ux.y = f2tf(vx.y); ux.z = f2tf(vx.z); ux.w = f2tf(vx.w);
            uh.x = f2tf(vh.x); uh.y = f2tf(vh.y); uh.z = f2tf(vh.z); uh.w = f2tf(vh.w);
            *(uint4*)(xs + row * XS_STRIDE + col4 * 4) = ux;
            *(uint4*)(hs + row * XS_STRIDE + col4 * 4) = uh;
        }
    }
    __syncthreads();

    float acc[4][2][2][4];     // [gate][mt][nt][e]
    const size_t TBH = (size_t)M_ * H_;

    for (int s = 0; s < NSTAGES; s++) {
        const int hblk = s >> 4;
        const int kc   = s & 15;
        const int buf  = s & 3;

        if (kc == 0) {
            #pragma unroll
            for (int gt = 0; gt < 4; gt++)
                #pragma unroll
                for (int mt = 0; mt < 2; mt++)
                    #pragma unroll
                    for (int nt = 0; nt < 2; nt++)
                        #pragma unroll
                        for (int e = 0; e < 4; e++) acc[gt][mt][nt][e] = 0.f;
        }

        // stage s ready: commits so far = 3 + s, keep <=2 pending
        asm volatile("cp.async.wait_group 2;" ::: "memory");
        __syncthreads();

        // refill buffer (s+3)&3 (held stage s-1; everyone is done with it)
        if (s + 3 < NSTAGES) {
            const int s3 = s + 3;
            const uint4* src = (const uint4*)(g_wscr + (size_t)s3 * W_SLICE_WORDS);
            uint32_t dst = ws_sa + (uint32_t)(s3 & 3) * (W_SLICE_WORDS * 4);
            for (int i = tid; i < 768; i += NTHREADS) {
                asm volatile("cp.async.ca.shared.global [%0], [%1], 16;"
                             :: "r"(dst + i * 16), "l"(src + i) : "memory");
            }
        }
        asm volatile("cp.async.commit_group;" ::: "memory");

        // ---- A fragments: 2 m-tiles x (x, hid) ---------------------------
        uint32_t ax[2][4], ah[2][4];
        {
            const int kw = kc * 8;
            #pragma unroll
            for (int mt = 0; mt < 2; mt++) {
                int r0 = wm * 32 + mt * 16 + g;
                const uint32_t* xr = xs + r0 * XS_STRIDE + kw + c;
                const uint32_t* hr = hs + r0 * XS_STRIDE + kw + c;
                ax[mt][0] = xr[0];              ax[mt][2] = xr[4];
                ax[mt][1] = xr[8 * XS_STRIDE];  ax[mt][3] = xr[8 * XS_STRIDE + 4];
                ah[mt][0] = hr[0];              ah[mt][2] = hr[4];
                ah[mt][1] = hr[8 * XS_STRIDE];  ah[mt][3] = hr[8 * XS_STRIDE + 4];
            }
        }

        // ---- 24 MMAs: j = {Wih_r, Wih_z, Wih_n, Whh_r, Whh_z, Whh_n} -----
        const uint32_t* wb = ws + buf * W_SLICE_WORDS;
        #pragma unroll
        for (int j = 0; j < 6; j++) {
            const int gate = (j == 0 || j == 3) ? 0 : (j == 1 || j == 4) ? 1
                           : (j == 2) ? 2 : 3;
            const uint32_t (*A)[4] = (j < 3) ? ax : ah;
            const uint32_t* wj = wb + j * 512;
            #pragma unroll
            for (int nt = 0; nt < 2; nt++) {
                uint32_t bfrag[2];
                *(uint64_t*)bfrag =
                    *(const uint64_t*)(wj + (wh * 16 + nt * 8 + g) * 8 + c * 2);
                mma_tf32(acc[gate][0][nt], A[0], bfrag);
                mma_tf32(acc[gate][1][nt], A[1], bfrag);
            }
        }

        // ---- epilogue at the end of each h-half --------------------------
        if (kc == 15) {
            const int h0 = hblk * 64;
            // stage combined biases (disjoint smem region; sync orders reads)
            if (tid < 256) {
                int which = tid >> 6, h = tid & 63;
                float v;
                if      (which == 0) v = b_ih[h0 + h]       + b_hh[h0 + h];
                else if (which == 1) v = b_ih[H_ + h0 + h]  + b_hh[H_ + h0 + h];
                else if (which == 2) v = b_ih[2 * H_ + h0 + h];
                else                 v = b_hh[2 * H_ + h0 + h];
                bias[which * 64 + h] = v;
            }
            __syncthreads();

            #pragma unroll
            for (int mt = 0; mt < 2; mt++) {
                #pragma unroll
                for (int nt = 0; nt < 2; nt++) {
                    int hl = wh * 16 + nt * 8 + 2 * c;        // local col (even)
                    float2 br4  = *(const float2*)(bias + hl);
                    float2 bz4  = *(const float2*)(bias + 64 + hl);
                    float2 bin4 = *(const float2*)(bias + 128 + hl);
                    float2 bhn4 = *(const float2*)(bias + 192 + hl);
                    #pragma unroll
                    for (int rr = 0; rr < 2; rr++) {
                        int m = bm + wm * 32 + mt * 16 + g + rr * 8;
                        size_t base = (size_t)m * H_ + h0 + hl;
                        float2 hv = __ldg((const float2*)(hid + base));
                        float yv[2];
                        #pragma unroll
                        for (int cc = 0; cc < 2; cc++) {
                            int e = rr * 2 + cc;
                            float brv  = cc ? br4.y  : br4.x;
                            float bzv  = cc ? bz4.y  : bz4.x;
                            float binv = cc ? bin4.y : bin4.x;
                            float bhnv = cc ? bhn4.y : bhn4.x;
                            float hvv  = cc ? hv.y   : hv.x;
                            float r = sigmoidf_(acc[0][mt][nt][e] + brv);
                            float z = sigmoidf_(acc[1][mt][nt][e] + bzv);
                            float n = tanhf_(acc[2][mt][nt][e] + binv
                                             + r * (acc[3][mt][nt][e] + bhnv));
                            yv[cc] = (1.0f - z) * n + z * hvv;
                        }
                        *(float2*)(out + base) = make_float2(yv[0], yv[1]);
                        *(float2*)(out + TBH + base) = hv;    // hid copy (exact)
                    }
                }
            }
        }
    }
}

// ---------------------------------------------------------------------------
extern "C" void kernel_launch(void* const* d_in, const int* in_sizes, int n_in,
                              void* d_out, int out_size) {
    (void)in_sizes; (void)n_in; (void)out_size;
    const float* x    = (const float*)d_in[0];
    const float* hid  = (const float*)d_in[1];
    const float* W_ih = (const float*)d_in[2];
    const float* W_hh = (const float*)d_in[3];
    const float* b_ih = (const float*)d_in[4];
    const float* b_hh = (const float*)d_in[5];
    float* out = (float*)d_out;

    gru_prep_w<<<98304 / 256, 256>>>(W_ih, W_hh);

    const int smem_bytes =
        (2 * BM * XS_STRIDE + 4 * W_SLICE_WORDS + 256) * (int)sizeof(float);
    cudaFuncSetAttribute(gru_main,
                         cudaFuncAttributeMaxDynamicSharedMemorySize, smem_bytes);
    gru_main<<<M_ / BM, NTHREADS, smem_bytes>>>(x, hid, b_ih, b_hh, out);
}

// round 6
// speedup vs baseline: 2.0075x; 1.0385x over previous
#include <cuda_runtime.h>
#include <cstdint>

// ============================================================================
// GRU per-timestep cell, batched: M = T*B = 131072, K = 128, H = 128.
//   r = sig(s_r + br), z = sig(s_z + bz), n = tanh(gi_n + bin + r*(gh_n + bhn))
//   y = (1-z)*n + z*hid ; out = concat(y, hid)
//
// tf32 mma.sync (m16n8k8), compute_103-safe.
// R6: 2 CTAs/SM for latency hiding. BM=64, 256 thr, 3-stage cp.async weight
// pipeline (105.5KB smem, <=128 regs). Warp tile 32m x 16h, 4 acc panels.
// Weights pre-converted to tf32 fragment-pair layout by prep kernel.
// ============================================================================

#define T_ 512
#define B_ 256
#define H_ 128
#define K_ 128
#define M_ (T_ * B_)            // 131072
#define BM 64
#define NTHREADS 256
#define XS_STRIDE 132           // 128 + 4 words pad
#define W_SLICE_WORDS 3072      // 6 mats * 64 h * 8 k (pair layout) per stage
#define NSTAGES 32              // 2 hblk * 16 kc
#define NBUF 3

// weight scratch: [hblk][kc][j][h][c][p]  (tf32 bits)
__device__ uint32_t g_wscr[2 * 16 * 6 * 64 * 8];   // 98304 words = 384 KB

__device__ __forceinline__ uint32_t f2tf(float f) {
    uint32_t u;
    asm("cvt.rna.tf32.f32 %0, %1;" : "=r"(u) : "f"(f));
    return u;
}

__device__ __forceinline__ void mma_tf32(float* c, const uint32_t* a, const uint32_t* b) {
    asm volatile(
        "mma.sync.aligned.m16n8k8.row.col.f32.tf32.tf32.f32 "
        "{%0,%1,%2,%3}, {%4,%5,%6,%7}, {%8,%9}, {%0,%1,%2,%3};"
        : "+f"(c[0]), "+f"(c[1]), "+f"(c[2]), "+f"(c[3])
        : "r"(a[0]), "r"(a[1]), "r"(a[2]), "r"(a[3]),
          "r"(b[0]), "r"(b[1]));
}

__device__ __forceinline__ uint32_t smem_u32(const void* p) {
    uint32_t a;
    asm("{ .reg .u64 t; cvta.to.shared.u64 t, %1; cvt.u32.u64 %0, t; }"
        : "=r"(a) : "l"(p));
    return a;
}

__device__ __forceinline__ float sigmoidf_(float x) {
    return 1.0f / (1.0f + __expf(-x));
}
__device__ __forceinline__ float tanhf_(float x) {
    float e = __expf(2.0f * x);          // saturates correctly at +-inf
    return 1.0f - 2.0f / (e + 1.0f);
}

// ---------------------------------------------------------------------------
// Prep: scatter W_ih/W_hh into tf32 fragment-pair layout.
//   idx = ((((hblk*16 + kc)*6 + j)*64 + h)*4 + c)*2 + p
//   value = W[(j%3)*128 + hblk*64 + h][kc*8 + c + p*4]
// ---------------------------------------------------------------------------
__global__ void gru_prep_w(const float* __restrict__ W_ih,
                           const float* __restrict__ W_hh) {
    int idx = blockIdx.x * 256 + threadIdx.x;        // 0..98303
    int p = idx & 1;
    int c = (idx >> 1) & 3;
    int h = (idx >> 3) & 63;
    int rest = idx >> 9;
    int j = rest % 6;
    int rest2 = rest / 6;
    int kc = rest2 & 15;
    int hblk = rest2 >> 4;
    int k = kc * 8 + c + p * 4;
    int row = (j % 3) * H_ + hblk * 64 + h;
    const float* W = (j < 3) ? W_ih : W_hh;
    g_wscr[idx] = f2tf(W[row * K_ + k]);
}

// ---------------------------------------------------------------------------
// Main fused kernel: 2 CTAs per SM.
// ---------------------------------------------------------------------------
__global__ void __launch_bounds__(NTHREADS, 2)
gru_main(const float* __restrict__ x,
         const float* __restrict__ hid,
         const float* __restrict__ b_ih,
         const float* __restrict__ b_hh,
         float* __restrict__ out)
{
    extern __shared__ char smem[];
    uint32_t* xs = (uint32_t*)smem;                  // [64][XS_STRIDE]
    uint32_t* hs = xs + BM * XS_STRIDE;
    uint32_t* ws = hs + BM * XS_STRIDE;              // [NBUF][W_SLICE_WORDS]
    float*  bias = (float*)(ws + NBUF * W_SLICE_WORDS); // br/bz/bin/bhn: 4 x 64

    const int tid  = threadIdx.x;
    const int warp = tid >> 5;
    const int lane = tid & 31;
    const int wm   = warp & 1;        // 0..1: 32-row slab
    const int wh   = warp >> 1;       // 0..3: 16-col slab
    const int g    = lane >> 2;       // 0..7
    const int c    = lane & 3;        // 0..3
    const int bm   = blockIdx.x * BM;

    const uint32_t ws_sa = smem_u32(ws);

    // ---- weight pipeline prologue: stages 0,1 ----------------------------
    #pragma unroll
    for (int s = 0; s < 2; s++) {
        const uint4* src = (const uint4*)(g_wscr + (size_t)s * W_SLICE_WORDS);
        uint32_t dst = ws_sa + (uint32_t)s * (W_SLICE_WORDS * 4);
        #pragma unroll
        for (int i = 0; i < 3; i++) {
            int e = i * NTHREADS + tid;              // 0..767
            asm volatile("cp.async.ca.shared.global [%0], [%1], 16;"
                         :: "r"(dst + e * 16), "l"(src + e) : "memory");
        }
        asm volatile("cp.async.commit_group;" ::: "memory");
    }

    // ---- load + convert x/hid tiles [64 x 128] ---------------------------
    {
        const float4* xg = (const float4*)(x   + (size_t)bm * K_);
        const float4* hg = (const float4*)(hid + (size_t)bm * K_);
        #pragma unroll
        for (int i = 0; i < 8; i++) {
            int idx  = i * NTHREADS + tid;       // 0..2047
            int row  = idx >> 5;                 // 32 float4 per row
            int col4 = idx & 31;
            float4 vx = xg[row * 32 + col4];
            float4 vh = hg[row * 32 + col4];
            uint4 ux, uh;
            ux.x = f2tf(vx.x); ux.y = f2tf(vx.y); ux.z = f2tf(vx.z); ux.w = f2tf(vx.w);
            uh.x = f2tf(vh.x); uh.y = f2tf(vh.y); uh.z = f2tf(vh.z); uh.w = f2tf(vh.w);
            *(uint4*)(xs + row * XS_STRIDE + col4 * 4) = ux;
            *(uint4*)(hs + row * XS_STRIDE + col4 * 4) = uh;
        }
    }
    __syncthreads();

    float acc[4][2][2][4];     // [gate][mt][nt][e]
    const size_t TBH = (size_t)M_ * H_;

    for (int s = 0; s < NSTAGES; s++) {
        const int hblk = s >> 4;
        const int kc   = s & 15;
        const int buf  = s % NBUF;

        if (kc == 0) {
            #pragma unroll
            for (int gt = 0; gt < 4; gt++)
                #pragma unroll
                for (int mt = 0; mt < 2; mt++)
                    #pragma unroll
                    for (int nt = 0; nt < 2; nt++)
                        #pragma unroll
                        for (int e = 0; e < 4; e++) acc[gt][mt][nt][e] = 0.f;
        }

        // stage s ready: commits so far = 2 + s, allow 1 pending
        asm volatile("cp.async.wait_group 1;" ::: "memory");
        __syncthreads();

        // refill buffer (s+2)%NBUF (held stage s-1; all warps are past it)
        if (s + 2 < NSTAGES) {
            const int s2 = s + 2;
            const uint4* src = (const uint4*)(g_wscr + (size_t)s2 * W_SLICE_WORDS);
            uint32_t dst = ws_sa + (uint32_t)(s2 % NBUF) * (W_SLICE_WORDS * 4);
            #pragma unroll
            for (int i = 0; i < 3; i++) {
                int e = i * NTHREADS + tid;
                asm volatile("cp.async.ca.shared.global [%0], [%1], 16;"
                             :: "r"(dst + e * 16), "l"(src + e) : "memory");
            }
        }
        asm volatile("cp.async.commit_group;" ::: "memory");

        // ---- A fragments: 2 m-tiles x (x, hid) ---------------------------
        uint32_t ax[2][4], ah[2][4];
        {
            const int kw = kc * 8;
            #pragma unroll
            for (int mt = 0; mt < 2; mt++) {
                int r0 = wm * 32 + mt * 16 + g;
                const uint32_t* xr = xs + r0 * XS_STRIDE + kw + c;
                const uint32_t* hr = hs + r0 * XS_STRIDE + kw + c;
                ax[mt][0] = xr[0];              ax[mt][2] = xr[4];
                ax[mt][1] = xr[8 * XS_STRIDE];  ax[mt][3] = xr[8 * XS_STRIDE + 4];
                ah[mt][0] = hr[0];              ah[mt][2] = hr[4];
                ah[mt][1] = hr[8 * XS_STRIDE];  ah[mt][3] = hr[8 * XS_STRIDE + 4];
            }
        }

        // ---- 24 MMAs: j = {Wih_r, Wih_z, Wih_n, Whh_r, Whh_z, Whh_n} -----
        const uint32_t* wb = ws + buf * W_SLICE_WORDS;
        #pragma unroll
        for (int j = 0; j < 6; j++) {
            const int gate = (j == 0 || j == 3) ? 0 : (j == 1 || j == 4) ? 1
                           : (j == 2) ? 2 : 3;
            const uint32_t (*A)[4] = (j < 3) ? ax : ah;
            const uint32_t* wj = wb + j * 512;
            #pragma unroll
            for (int nt = 0; nt < 2; nt++) {
                uint32_t bfrag[2];
                *(uint64_t*)bfrag =
                    *(const uint64_t*)(wj + (wh * 16 + nt * 8 + g) * 8 + c * 2);
                mma_tf32(acc[gate][0][nt], A[0], bfrag);
                mma_tf32(acc[gate][1][nt], A[1], bfrag);
            }
        }

        // ---- epilogue at the end of each h-half --------------------------
        if (kc == 15) {
            const int h0 = hblk * 64;
            {
                int which = tid >> 6, h = tid & 63;    // 256 thr = all 4 slots
                float v;
                if      (which == 0) v = b_ih[h0 + h]       + b_hh[h0 + h];
                else if (which == 1) v = b_ih[H_ + h0 + h]  + b_hh[H_ + h0 + h];
                else if (which == 2) v = b_ih[2 * H_ + h0 + h];
                else                 v = b_hh[2 * H_ + h0 + h];
                bias[which * 64 + h] = v;
            }
            __syncthreads();

            #pragma unroll
            for (int mt = 0; mt < 2; mt++) {
                #pragma unroll
                for (int nt = 0; nt < 2; nt++) {
                    int hl = wh * 16 + nt * 8 + 2 * c;        // local col (even)
                    float2 br4  = *(const float2*)(bias + hl);
                    float2 bz4  = *(const float2*)(bias + 64 + hl);
                    float2 bin4 = *(const float2*)(bias + 128 + hl);
                    float2 bhn4 = *(const float2*)(bias + 192 + hl);
                    #pragma unroll
                    for (int rr = 0; rr < 2; rr++) {
                        int m = bm + wm * 32 + mt * 16 + g + rr * 8;
                        size_t base = (size_t)m * H_ + h0 + hl;
                        float2 hv = __ldg((const float2*)(hid + base));
                        float yv[2];
                        #pragma unroll
                        for (int cc = 0; cc < 2; cc++) {
                            int e = rr * 2 + cc;
                            float brv  = cc ? br4.y  : br4.x;
                            float bzv  = cc ? bz4.y  : bz4.x;
                            float binv = cc ? bin4.y : bin4.x;
                            float bhnv = cc ? bhn4.y : bhn4.x;
                            float hvv  = cc ? hv.y   : hv.x;
                            float r = sigmoidf_(acc[0][mt][nt][e] + brv);
                            float z = sigmoidf_(acc[1][mt][nt][e] + bzv);
                            float n = tanhf_(acc[2][mt][nt][e] + binv
                                             + r * (acc[3][mt][nt][e] + bhnv));
                            yv[cc] = (1.0f - z) * n + z * hvv;
                        }
                        *(float2*)(out + base) = make_float2(yv[0], yv[1]);
                        *(float2*)(out + TBH + base) = hv;    // hid copy (exact)
                    }
                }
            }
            __syncthreads();   // bias region stable before next hblk reuses it
        }
    }
}

// ---------------------------------------------------------------------------
extern "C" void kernel_launch(void* const* d_in, const int* in_sizes, int n_in,
                              void* d_out, int out_size) {
    (void)in_sizes; (void)n_in; (void)out_size;
    const float* x    = (const float*)d_in[0];
    const float* hid  = (const float*)d_in[1];
    const float* W_ih = (const float*)d_in[2];
    const float* W_hh = (const float*)d_in[3];
    const float* b_ih = (const float*)d_in[4];
    const float* b_hh = (const float*)d_in[5];
    float* out = (float*)d_out;

    gru_prep_w<<<98304 / 256, 256>>>(W_ih, W_hh);

    const int smem_bytes =
        (2 * BM * XS_STRIDE + NBUF * W_SLICE_WORDS + 256) * (int)sizeof(float);
    cudaFuncSetAttribute(gru_main,
                         cudaFuncAttributeMaxDynamicSharedMemorySize, smem_bytes);
    gru_main<<<M_ / BM, NTHREADS, smem_bytes>>>(x, hid, b_ih, b_hh, out);
}

// round 9
// speedup vs baseline: 2.0952x; 1.0437x over previous
#include <cuda_runtime.h>
#include <cstdint>

// ============================================================================
// GRU per-timestep cell, batched: M = T*B = 131072, K = 128, H = 128.
//   r = sig(s_r + br), z = sig(s_z + bz), n = tanh(gi_n + bin + r*(gh_n + bhn))
//   y = (1-z)*n + z*hid ; out = concat(y, hid)
//
// tf32 mma.sync (m16n8k8), compute_103-safe.
// R9: barrier-free mainloop with FULLY PRIVATE per-warp weight slices
// (fixes R7/R8 cross-warp cp.async race). Tile smem uses rotation swizzle
// (k + 4r) & 127 instead of padding -> 112KB total, 2 CTAs/SM.
// A-fragments software-pipelined one stage ahead; per-warp commit-group
// waits; pre-combined biases; single __syncthreads after tile load.
// ============================================================================

#define T_ 512
#define B_ 256
#define H_ 128
#define K_ 128
#define M_ (T_ * B_)            // 131072
#define BM 64
#define NTHREADS 256
#define SLICE_WORDS 768         // per (stage, wh): 6 mats * 16 h * 8 k
#define NSTAGES 32              // 2 hblk * 16 kc

// weight scratch: [stage(hblk,kc)][wh][j][h16][c][p]  (tf32 bits)
__device__ uint32_t g_wscr[NSTAGES * 4 * SLICE_WORDS];   // 98304 words = 384 KB
// combined biases: [which][h]  which: 0=b_r, 1=b_z, 2=b_in, 3=b_hn
__device__ float g_bias[4 * H_];

__device__ __forceinline__ uint32_t f2tf(float f) {
    uint32_t u;
    asm("cvt.rna.tf32.f32 %0, %1;" : "=r"(u) : "f"(f));
    return u;
}

__device__ __forceinline__ void mma_tf32(float* c, const uint32_t* a, const uint32_t* b) {
    asm volatile(
        "mma.sync.aligned.m16n8k8.row.col.f32.tf32.tf32.f32 "
        "{%0,%1,%2,%3}, {%4,%5,%6,%7}, {%8,%9}, {%0,%1,%2,%3};"
        : "+f"(c[0]), "+f"(c[1]), "+f"(c[2]), "+f"(c[3])
        : "r"(a[0]), "r"(a[1]), "r"(a[2]), "r"(a[3]),
          "r"(b[0]), "r"(b[1]));
}

__device__ __forceinline__ uint32_t smem_u32(const void* p) {
    uint32_t a;
    asm("{ .reg .u64 t; cvta.to.shared.u64 t, %1; cvt.u32.u64 %0, t; }"
        : "=r"(a) : "l"(p));
    return a;
}

__device__ __forceinline__ float sigmoidf_(float x) {
    return 1.0f / (1.0f + __expf(-x));
}
__device__ __forceinline__ float tanhf_(float x) {
    float e = __expf(2.0f * x);          // saturates correctly at +-inf
    return 1.0f - 2.0f / (e + 1.0f);
}

// tile rotation swizzle: element (r, k) -> word offset r*128 + ((k + 4r) & 127)
__device__ __forceinline__ int xsw(int r, int k) {
    return r * 128 + ((k + 4 * r) & 127);
}

// ---------------------------------------------------------------------------
// Prep: scatter W_ih/W_hh into tf32 warp-sliced fragment-pair layout + biases.
//   idx = (s*4 + wh)*768 + j*128 + h16*8 + c*2 + p   (s = hblk*16 + kc)
//   value = W[(j%3)*128 + hblk*64 + wh*16 + h16][kc*8 + c + p*4]
// ---------------------------------------------------------------------------
__global__ void gru_prep_w(const float* __restrict__ W_ih,
                           const float* __restrict__ W_hh,
                           const float* __restrict__ b_ih,
                           const float* __restrict__ b_hh) {
    int idx = blockIdx.x * 256 + threadIdx.x;        // 0..98303
    int within = idx % SLICE_WORDS;
    int slice  = idx / SLICE_WORDS;
    int p   = within & 1;
    int c   = (within >> 1) & 3;
    int h16 = (within >> 3) & 15;
    int j   = within >> 7;                           // 0..5
    int wh  = slice & 3;
    int kc  = (slice >> 2) & 15;
    int hblk = slice >> 6;
    int row = (j % 3) * H_ + hblk * 64 + wh * 16 + h16;
    int k = kc * 8 + c + p * 4;
    const float* W = (j < 3) ? W_ih : W_hh;
    g_wscr[idx] = f2tf(W[row * K_ + k]);

    if (idx < 4 * H_) {
        int which = idx >> 7, h = idx & 127;
        float v;
        if      (which == 0) v = b_ih[h]          + b_hh[h];
        else if (which == 1) v = b_ih[H_ + h]     + b_hh[H_ + h];
        else if (which == 2) v = b_ih[2 * H_ + h];
        else                 v = b_hh[2 * H_ + h];
        g_bias[idx] = v;
    }
}

// ---------------------------------------------------------------------------
// Main fused kernel: barrier-free mainloop, private per-warp slices, 2 CTAs/SM.
// ---------------------------------------------------------------------------
__global__ void __launch_bounds__(NTHREADS, 2)
gru_main(const float* __restrict__ x,
         const float* __restrict__ hid,
         float* __restrict__ out)
{
    extern __shared__ char smem[];
    uint32_t* xs = (uint32_t*)smem;                  // [64][128] swizzled
    uint32_t* hs = xs + BM * 128;
    uint32_t* ws = hs + BM * 128;                    // [8 warp][2 buf][768]

    const int tid  = threadIdx.x;
    const int warp = tid >> 5;
    const int lane = tid & 31;
    const int wm   = warp & 1;        // 0..1: 32-row slab
    const int wh   = warp >> 1;       // 0..3: 16-col slab
    const int g    = lane >> 2;       // 0..7
    const int c    = lane & 3;        // 0..3
    const int bm   = blockIdx.x * BM;

    // PRIVATE per-warp weight slice (no cross-warp smem sharing => no race)
    const uint32_t my_ws_sa = smem_u32(ws) + (uint32_t)warp * (2 * SLICE_WORDS * 4);
    const uint32_t* my_ws   = ws + warp * (2 * SLICE_WORDS);

    // ---- per-warp weight pipeline prologue: stages 0,1 -------------------
    #pragma unroll
    for (int s = 0; s < 2; s++) {
        const uint4* src = (const uint4*)(g_wscr + ((size_t)s * 4 + wh) * SLICE_WORDS);
        uint32_t dst = my_ws_sa + (uint32_t)s * (SLICE_WORDS * 4);
        #pragma unroll
        for (int i = 0; i < 6; i++) {                // 192 uint4 / 32 lanes
            int e = i * 32 + lane;
            asm volatile("cp.async.ca.shared.global [%0], [%1], 16;"
                         :: "r"(dst + e * 16), "l"(src + e) : "memory");
        }
        asm volatile("cp.async.commit_group;" ::: "memory");
    }

    // ---- load + convert x/hid tiles [64 x 128], rotation swizzle ---------
    {
        const float4* xg = (const float4*)(x   + (size_t)bm * K_);
        const float4* hg = (const float4*)(hid + (size_t)bm * K_);
        #pragma unroll
        for (int i = 0; i < 8; i++) {
            int idx  = i * NTHREADS + tid;       // 0..2047
            int row  = idx >> 5;
            int col4 = idx & 31;
            float4 vx = xg[row * 32 + col4];
            float4 vh = hg[row * 32 + col4];
            uint4 ux, uh;
            ux.x = f2tf(vx.x); ux.y = f2tf(vx.y); ux.z = f2tf(vx.z); ux.w = f2tf(vx.w);
            uh.x = f2tf(vh.x); uh.y = f2tf(vh.y); uh.z = f2tf(vh.z); uh.w = f2tf(vh.w);
            int off = xsw(row, col4 * 4);        // 16B-aligned (4*r & rotation mult of 4)
            *(uint4*)(xs + off) = ux;
            *(uint4*)(hs + off) = uh;
        }
    }
    __syncthreads();     // the ONLY block-wide barrier

    // ---- A fragment pipeline: load stage 0 (kc=0) ------------------------
    const int r0a = wm * 32 + g;          // mt=0 row
    const int r0b = wm * 32 + 16 + g;     // mt=1 row
    uint32_t ax[2][4], ah[2][4];
    {
        ax[0][0] = xs[xsw(r0a,     c)];     ax[0][2] = xs[xsw(r0a,     c + 4)];
        ax[0][1] = xs[xsw(r0a + 8, c)];     ax[0][3] = xs[xsw(r0a + 8, c + 4)];
        ax[1][0] = xs[xsw(r0b,     c)];     ax[1][2] = xs[xsw(r0b,     c + 4)];
        ax[1][1] = xs[xsw(r0b + 8, c)];     ax[1][3] = xs[xsw(r0b + 8, c + 4)];
        ah[0][0] = hs[xsw(r0a,     c)];     ah[0][2] = hs[xsw(r0a,     c + 4)];
        ah[0][1] = hs[xsw(r0a + 8, c)];     ah[0][3] = hs[xsw(r0a + 8, c + 4)];
        ah[1][0] = hs[xsw(r0b,     c)];     ah[1][2] = hs[xsw(r0b,     c + 4)];
        ah[1][1] = hs[xsw(r0b + 8, c)];     ah[1][3] = hs[xsw(r0b + 8, c + 4)];
    }

    float acc[4][2][2][4];     // [gate][mt][nt][e]
    const size_t TBH = (size_t)M_ * H_;

    for (int s = 0; s < NSTAGES; s++) {
        const int hblk = s >> 4;
        const int kc   = s & 15;
        const int buf  = s & 1;

        if (kc == 0) {
            #pragma unroll
            for (int gt = 0; gt < 4; gt++)
                #pragma unroll
                for (int mt = 0; mt < 2; mt++)
                    #pragma unroll
                    for (int nt = 0; nt < 2; nt++)
                        #pragma unroll
                        for (int e = 0; e < 4; e++) acc[gt][mt][nt][e] = 0.f;
        }

        // weights for stage s ready (2 groups pending -> wait oldest).
        // Only THIS warp's buffers are involved; no cross-warp visibility needed.
        asm volatile("cp.async.wait_group 1;" ::: "memory");

        // ---- prefetch A fragments for stage s+1 (kc' = (s+1)&15) ---------
        uint32_t axn[2][4], ahn[2][4];
        {
            const int kw = ((s + 1) & 15) * 8;
            axn[0][0] = xs[xsw(r0a,     kw + c)];
            axn[0][2] = xs[xsw(r0a,     kw + c + 4)];
            axn[0][1] = xs[xsw(r0a + 8, kw + c)];
            axn[0][3] = xs[xsw(r0a + 8, kw + c + 4)];
            axn[1][0] = xs[xsw(r0b,     kw + c)];
            axn[1][2] = xs[xsw(r0b,     kw + c + 4)];
            axn[1][1] = xs[xsw(r0b + 8, kw + c)];
            axn[1][3] = xs[xsw(r0b + 8, kw + c + 4)];
            ahn[0][0] = hs[xsw(r0a,     kw + c)];
            ahn[0][2] = hs[xsw(r0a,     kw + c + 4)];
            ahn[0][1] = hs[xsw(r0a + 8, kw + c)];
            ahn[0][3] = hs[xsw(r0a + 8, kw + c + 4)];
            ahn[1][0] = hs[xsw(r0b,     kw + c)];
            ahn[1][2] = hs[xsw(r0b,     kw + c + 4)];
            ahn[1][1] = hs[xsw(r0b + 8, kw + c)];
            ahn[1][3] = hs[xsw(r0b + 8, kw + c + 4)];
        }

        // ---- 24 MMAs: j = {Wih_r, Wih_z, Wih_n, Whh_r, Whh_z, Whh_n} -----
        const uint32_t* wb = my_ws + buf * SLICE_WORDS;
        #pragma unroll
        for (int j = 0; j < 6; j++) {
            const int gate = (j == 0 || j == 3) ? 0 : (j == 1 || j == 4) ? 1
                           : (j == 2) ? 2 : 3;
            const uint32_t (*A)[4] = (j < 3) ? ax : ah;
            const uint32_t* wj = wb + j * 128;
            #pragma unroll
            for (int nt = 0; nt < 2; nt++) {
                uint32_t bfrag[2];
                *(uint64_t*)bfrag =
                    *(const uint64_t*)(wj + (nt * 8 + g) * 8 + c * 2);
                mma_tf32(acc[gate][0][nt], A[0], bfrag);
                mma_tf32(acc[gate][1][nt], A[1], bfrag);
            }
        }

        // ---- issue weights for stage s+2 into the buffer just drained ----
        if (s + 2 < NSTAGES) {
            const int s2 = s + 2;
            const uint4* src =
                (const uint4*)(g_wscr + ((size_t)s2 * 4 + wh) * SLICE_WORDS);
            uint32_t dst = my_ws_sa + (uint32_t)(s2 & 1) * (SLICE_WORDS * 4);
            #pragma unroll
            for (int i = 0; i < 6; i++) {
                int e = i * 32 + lane;
                asm volatile("cp.async.ca.shared.global [%0], [%1], 16;"
                             :: "r"(dst + e * 16), "l"(src + e) : "memory");
            }
        }
        asm volatile("cp.async.commit_group;" ::: "memory");

        // rotate A pipeline
        #pragma unroll
        for (int mt = 0; mt < 2; mt++)
            #pragma unroll
            for (int e = 0; e < 4; e++) {
                ax[mt][e] = axn[mt][e];
                ah[mt][e] = ahn[mt][e];
            }

        // ---- epilogue at the end of each h-half --------------------------
        if (kc == 15) {
            const int h0 = hblk * 64;
            #pragma unroll
            for (int nt = 0; nt < 2; nt++) {
                int hg_ = h0 + wh * 16 + nt * 8 + 2 * c;   // global h (even)
                float2 brv  = __ldg((const float2*)(g_bias + hg_));
                float2 bzv  = __ldg((const float2*)(g_bias + H_ + hg_));
                float2 binv = __ldg((const float2*)(g_bias + 2 * H_ + hg_));
                float2 bhnv = __ldg((const float2*)(g_bias + 3 * H_ + hg_));
                #pragma unroll
                for (int mt = 0; mt < 2; mt++) {
                    #pragma unroll
                    for (int rr = 0; rr < 2; rr++) {
                        int m = bm + wm * 32 + mt * 16 + g + rr * 8;
                        size_t base = (size_t)m * H_ + hg_;
                        float2 hv = __ldg((const float2*)(hid + base));
                        float yv[2];
                        #pragma unroll
                        for (int cc = 0; cc < 2; cc++) {
                            int e = rr * 2 + cc;
                            float r = sigmoidf_(acc[0][mt][nt][e]
                                                + (cc ? brv.y : brv.x));
                            float z = sigmoidf_(acc[1][mt][nt][e]
                                                + (cc ? bzv.y : bzv.x));
                            float n = tanhf_(acc[2][mt][nt][e]
                                             + (cc ? binv.y : binv.x)
                                             + r * (acc[3][mt][nt][e]
                                                    + (cc ? bhnv.y : bhnv.x)));
                            yv[cc] = (1.0f - z) * n + z * (cc ? hv.y : hv.x);
                        }
                        *(float2*)(out + base) = make_float2(yv[0], yv[1]);
                        *(float2*)(out + TBH + base) = hv;   // hid copy (exact)
                    }
                }
            }
        }
    }
}

// ---------------------------------------------------------------------------
extern "C" void kernel_launch(void* const* d_in, const int* in_sizes, int n_in,
                              void* d_out, int out_size) {
    (void)in_sizes; (void)n_in; (void)out_size;
    const float* x    = (const float*)d_in[0];
    const float* hid  = (const float*)d_in[1];
    const float* W_ih = (const float*)d_in[2];
    const float* W_hh = (const float*)d_in[3];
    const float* b_ih = (const float*)d_in[4];
    const float* b_hh = (const float*)d_in[5];
    float* out = (float*)d_out;

    gru_prep_w<<<98304 / 256, 256>>>(W_ih, W_hh, b_ih, b_hh);

    const int smem_bytes =
        (2 * BM * 128 + 8 * 2 * SLICE_WORDS) * (int)sizeof(float);   // 112 KB
    cudaFuncSetAttribute(gru_main,
                         cudaFuncAttributeMaxDynamicSharedMemorySize, smem_bytes);
    gru_main<<<M_ / BM, NTHREADS, smem_bytes>>>(x, hid, out);
}

// round 13
// speedup vs baseline: 2.1451x; 1.0238x over previous
#include <cuda_runtime.h>
#include <cstdint>

// ============================================================================
// GRU per-timestep cell, batched: M = T*B = 131072, K = 128, H = 128.
//   r = sig(s_r + br), z = sig(s_z + bz), n = tanh(gi_n + bin + r*(gh_n + bhn))
//   y = (1-z)*n + z*hid ; out = concat(y, hid)
//
// tf32 mma.sync (m16n8k8), compute_103-safe.
// R10: producer/consumer weight pipeline (one cp.async stream per warp-pair,
// named-barrier handoff: race-free at half the L1 traffic of R9).
// A-tiles in conflict-free fragment-pair layout -> 8 LDS.64 per stage
// (was 16 LDS.32). 2-kc pipeline steps (16 waits instead of 32).
// BM=64, 256 thr, 2 CTAs/SM, smem 112KB.
// ============================================================================

#define T_ 512
#define B_ 256
#define H_ 128
#define K_ 128
#define M_ (T_ * B_)            // 131072
#define BM 64
#define NTHREADS 256
#define SLICE2 1536             // per (step, wh): 2 kc * 6 mats * 16 h * 8 k
#define WSTEPS 16               // 2 hblk * 8 kc-pairs

// weight scratch: [step t][wh][kcsub][j][h16][c][p]  (tf32 bits)
__device__ uint32_t g_wscr[WSTEPS * 4 * SLICE2];   // 98304 words = 384 KB
// combined biases: [which][h]  which: 0=b_r, 1=b_z, 2=b_in, 3=b_hn
__device__ float g_bias[4 * H_];

__device__ __forceinline__ uint32_t f2tf(float f) {
    uint32_t u;
    asm("cvt.rna.tf32.f32 %0, %1;" : "=r"(u) : "f"(f));
    return u;
}

__device__ __forceinline__ void mma_tf32(float* c, const uint32_t* a, const uint32_t* b) {
    asm volatile(
        "mma.sync.aligned.m16n8k8.row.col.f32.tf32.tf32.f32 "
        "{%0,%1,%2,%3}, {%4,%5,%6,%7}, {%8,%9}, {%0,%1,%2,%3};"
        : "+f"(c[0]), "+f"(c[1]), "+f"(c[2]), "+f"(c[3])
        : "r"(a[0]), "r"(a[1]), "r"(a[2]), "r"(a[3]),
          "r"(b[0]), "r"(b[1]));
}

__device__ __forceinline__ uint32_t smem_u32(const void* p) {
    uint32_t a;
    asm("{ .reg .u64 t; cvta.to.shared.u64 t, %1; cvt.u32.u64 %0, t; }"
        : "=r"(a) : "l"(p));
    return a;
}

#define BARW(id) asm volatile("bar.sync %0, 64;" :: "r"(id) : "memory")

__device__ __forceinline__ float sigmoidf_(float x) {
    return 1.0f / (1.0f + __expf(-x));
}
__device__ __forceinline__ float tanhf_(float x) {
    float e = __expf(2.0f * x);          // saturates correctly at +-inf
    return 1.0f - 2.0f / (e + 1.0f);
}

// A-tile fragment-pair layout, conflict-free for STS.32 stores and LDS.64 loads:
//   element (r, col) with col = kc*8 + c + 4p  lives at
//   r*128 + (((kc + r) * 8) & 127) + ((c + (kc>>2)) & 3)*2 + p
__device__ __forceinline__ int apair_off(int r, int kc, int c) {
    return r * 128 + (((kc + r) * 8) & 127) + (((c + (kc >> 2)) & 3) << 1);
}

// ---------------------------------------------------------------------------
// Prep: scatter W_ih/W_hh into tf32 step-sliced fragment-pair layout + biases.
//   idx = (((t*4 + wh)*2 + kcsub)*6 + j)*128 + h16*8 + c*2 + p
//   kc = (t&7)*2 + kcsub, hblk = t>>3
//   value = W[(j%3)*128 + hblk*64 + wh*16 + h16][kc*8 + c + p*4]
// ---------------------------------------------------------------------------
__global__ void gru_prep_w(const float* __restrict__ W_ih,
                           const float* __restrict__ W_hh,
                           const float* __restrict__ b_ih,
                           const float* __restrict__ b_hh) {
    int idx = blockIdx.x * 256 + threadIdx.x;        // 0..98303
    int within = idx % 768;
    int blk    = idx / 768;
    int p   = within & 1;
    int c   = (within >> 1) & 3;
    int h16 = (within >> 3) & 15;
    int j   = within >> 7;                           // 0..5
    int kcsub = blk & 1;
    int wh    = (blk >> 1) & 3;
    int t     = blk >> 3;                            // 0..15
    int hblk  = t >> 3;
    int kc    = (t & 7) * 2 + kcsub;
    int row = (j % 3) * H_ + hblk * 64 + wh * 16 + h16;
    int k = kc * 8 + c + p * 4;
    const float* W = (j < 3) ? W_ih : W_hh;
    g_wscr[idx] = f2tf(W[row * K_ + k]);

    if (idx < 4 * H_) {
        int which = idx >> 7, h = idx & 127;
        float v;
        if      (which == 0) v = b_ih[h]          + b_hh[h];
        else if (which == 1) v = b_ih[H_ + h]     + b_hh[H_ + h];
        else if (which == 2) v = b_ih[2 * H_ + h];
        else                 v = b_hh[2 * H_ + h];
        g_bias[idx] = v;
    }
}

// ---------------------------------------------------------------------------
// Main fused kernel: producer/consumer weight pipeline, 2 CTAs/SM.
// ---------------------------------------------------------------------------
__global__ void __launch_bounds__(NTHREADS, 2)
gru_main(const float* __restrict__ x,
         const float* __restrict__ hid,
         float* __restrict__ out)
{
    extern __shared__ char smem[];
    uint32_t* xs = (uint32_t*)smem;                  // [64][128] pair layout
    uint32_t* hs = xs + BM * 128;
    uint32_t* ws = hs + BM * 128;                    // [4 wh][2 buf][1536]

    const int tid  = threadIdx.x;
    const int warp = tid >> 5;
    const int lane = tid & 31;
    const int wm   = warp & 1;        // 0..1: 32-row slab; wm==0 is producer
    const int wh   = warp >> 1;       // 0..3: 16-col slab
    const int g    = lane >> 2;       // 0..7
    const int c    = lane & 3;        // 0..3
    const int bm   = blockIdx.x * BM;
    const int barid = 1 + wh;         // named barrier per warp pair

    // Weight slice shared by the wm-pair of this wh (producer fills it)
    const uint32_t my_ws_sa = smem_u32(ws) + (uint32_t)wh * (2 * SLICE2 * 4);
    const uint32_t* my_ws   = ws + wh * (2 * SLICE2);

    // ---- producer prologue: steps 0,1 ------------------------------------
    if (wm == 0) {
        #pragma unroll
        for (int t = 0; t < 2; t++) {
            const uint4* src = (const uint4*)(g_wscr + ((size_t)t * 4 + wh) * SLICE2);
            uint32_t dst = my_ws_sa + (uint32_t)t * (SLICE2 * 4);
            #pragma unroll
            for (int i = 0; i < 12; i++) {           // 384 uint4 / 32 lanes
                int e = i * 32 + lane;
                asm volatile("cp.async.ca.shared.global [%0], [%1], 16;"
                             :: "r"(dst + e * 16), "l"(src + e) : "memory");
            }
            asm volatile("cp.async.commit_group;" ::: "memory");
        }
    }

    // ---- load + convert x/hid tiles [64 x 128] into pair layout ----------
    {
        const float4* xg = (const float4*)(x   + (size_t)bm * K_);
        const float4* hg = (const float4*)(hid + (size_t)bm * K_);
        #pragma unroll
        for (int i = 0; i < 8; i++) {
            int idx  = i * NTHREADS + tid;       // 0..2047
            int row  = idx >> 5;
            int q    = idx & 31;                 // float4 index within row
            float4 vx = xg[row * 32 + q];
            float4 vh = hg[row * 32 + q];
            int kc = q >> 1, p = q & 1, kk = kc >> 2;
            int base = row * 128 + (((kc + row) * 8) & 127) + p;
            xs[base + ((0 + kk) & 3) * 2] = f2tf(vx.x);
            xs[base + ((1 + kk) & 3) * 2] = f2tf(vx.y);
            xs[base + ((2 + kk) & 3) * 2] = f2tf(vx.z);
            xs[base + ((3 + kk) & 3) * 2] = f2tf(vx.w);
            hs[base + ((0 + kk) & 3) * 2] = f2tf(vh.x);
            hs[base + ((1 + kk) & 3) * 2] = f2tf(vh.y);
            hs[base + ((2 + kk) & 3) * 2] = f2tf(vh.z);
            hs[base + ((3 + kk) & 3) * 2] = f2tf(vh.w);
        }
    }
    __syncthreads();     // the ONLY block-wide barrier

    // ---- A fragment pipeline: load kc=0 ----------------------------------
    const int r0a = wm * 32 + g;          // mt=0 row
    const int r0b = wm * 32 + 16 + g;     // mt=1 row
    uint32_t ax[2][4], ah[2][4];
    {
        uint2 v;
        v = *(const uint2*)(xs + apair_off(r0a,     0, c)); ax[0][0]=v.x; ax[0][2]=v.y;
        v = *(const uint2*)(xs + apair_off(r0a + 8, 0, c)); ax[0][1]=v.x; ax[0][3]=v.y;
        v = *(const uint2*)(xs + apair_off(r0b,     0, c)); ax[1][0]=v.x; ax[1][2]=v.y;
        v = *(const uint2*)(xs + apair_off(r0b + 8, 0, c)); ax[1][1]=v.x; ax[1][3]=v.y;
        v = *(const uint2*)(hs + apair_off(r0a,     0, c)); ah[0][0]=v.x; ah[0][2]=v.y;
        v = *(const uint2*)(hs + apair_off(r0a + 8, 0, c)); ah[0][1]=v.x; ah[0][3]=v.y;
        v = *(const uint2*)(hs + apair_off(r0b,     0, c)); ah[1][0]=v.x; ah[1][2]=v.y;
        v = *(const uint2*)(hs + apair_off(r0b + 8, 0, c)); ah[1][1]=v.x; ah[1][3]=v.y;
    }

    float acc[4][2][2][4];     // [gate][mt][nt][e]
    const size_t TBH = (size_t)M_ * H_;

    for (int t = 0; t < WSTEPS; t++) {
        const int buf  = t & 1;
        const int hblk = t >> 3;

        // weights for step t ready (producer waits own groups, then handoff)
        if (wm == 0)
            asm volatile("cp.async.wait_group 1;" ::: "memory");
        BARW(barid);

        #pragma unroll
        for (int kcsub = 0; kcsub < 2; kcsub++) {
            const int kc = (t & 7) * 2 + kcsub;

            if (kc == 0) {
                #pragma unroll
                for (int gt = 0; gt < 4; gt++)
                    #pragma unroll
                    for (int mt = 0; mt < 2; mt++)
                        #pragma unroll
                        for (int nt = 0; nt < 2; nt++)
                            #pragma unroll
                            for (int e = 0; e < 4; e++) acc[gt][mt][nt][e] = 0.f;
            }

            // ---- prefetch A fragments for next kc in sequence ------------
            uint32_t axn[2][4], ahn[2][4];
            {
                const int kn = (kc + 1) & 15;
                uint2 v;
                v = *(const uint2*)(xs + apair_off(r0a,     kn, c)); axn[0][0]=v.x; axn[0][2]=v.y;
                v = *(const uint2*)(xs + apair_off(r0a + 8, kn, c)); axn[0][1]=v.x; axn[0][3]=v.y;
                v = *(const uint2*)(xs + apair_off(r0b,     kn, c)); axn[1][0]=v.x; axn[1][2]=v.y;
                v = *(const uint2*)(xs + apair_off(r0b + 8, kn, c)); axn[1][1]=v.x; axn[1][3]=v.y;
                v = *(const uint2*)(hs + apair_off(r0a,     kn, c)); ahn[0][0]=v.x; ahn[0][2]=v.y;
                v = *(const uint2*)(hs + apair_off(r0a + 8, kn, c)); ahn[0][1]=v.x; ahn[0][3]=v.y;
                v = *(const uint2*)(hs + apair_off(r0b,     kn, c)); ahn[1][0]=v.x; ahn[1][2]=v.y;
                v = *(const uint2*)(hs + apair_off(r0b + 8, kn, c)); ahn[1][1]=v.x; ahn[1][3]=v.y;
            }

            // ---- 24 MMAs ------------------------------------------------
            const uint32_t* wb = my_ws + buf * SLICE2 + kcsub * 768;
            #pragma unroll
            for (int j = 0; j < 6; j++) {
                const int gate = (j == 0 || j == 3) ? 0 : (j == 1 || j == 4) ? 1
                               : (j == 2) ? 2 : 3;
                const uint32_t (*A)[4] = (j < 3) ? ax : ah;
                const uint32_t* wj = wb + j * 128;
                #pragma unroll
                for (int nt = 0; nt < 2; nt++) {
                    uint32_t bfrag[2];
                    *(uint64_t*)bfrag =
                        *(const uint64_t*)(wj + (nt * 8 + g) * 8 + c * 2);
                    mma_tf32(acc[gate][0][nt], A[0], bfrag);
                    mma_tf32(acc[gate][1][nt], A[1], bfrag);
                }
            }

            // rotate A pipeline
            #pragma unroll
            for (int mt = 0; mt < 2; mt++)
                #pragma unroll
                for (int e = 0; e < 4; e++) {
                    ax[mt][e] = axn[mt][e];
                    ah[mt][e] = ahn[mt][e];
                }

            // ---- epilogue at the end of each h-half ----------------------
            if (kc == 15) {
                const int h0 = hblk * 64;
                #pragma unroll
                for (int nt = 0; nt < 2; nt++) {
                    int hg_ = h0 + wh * 16 + nt * 8 + 2 * c;   // global h (even)
                    float2 brv  = __ldg((const float2*)(g_bias + hg_));
                    float2 bzv  = __ldg((const float2*)(g_bias + H_ + hg_));
                    float2 binv = __ldg((const float2*)(g_bias + 2 * H_ + hg_));
                    float2 bhnv = __ldg((const float2*)(g_bias + 3 * H_ + hg_));
                    #pragma unroll
                    for (int mt = 0; mt < 2; mt++) {
                        #pragma unroll
                        for (int rr = 0; rr < 2; rr++) {
                            int m = bm + wm * 32 + mt * 16 + g + rr * 8;
                            size_t base = (size_t)m * H_ + hg_;
                            float2 hv = __ldg((const float2*)(hid + base));
                            float yv[2];
                            #pragma unroll
                            for (int cc = 0; cc < 2; cc++) {
                                int e = rr * 2 + cc;
                                float r = sigmoidf_(acc[0][mt][nt][e]
                                                    + (cc ? brv.y : brv.x));
                                float z = sigmoidf_(acc[1][mt][nt][e]
                                                    + (cc ? bzv.y : bzv.x));
                                float n = tanhf_(acc[2][mt][nt][e]
                                                 + (cc ? binv.y : binv.x)
                                                 + r * (acc[3][mt][nt][e]
                                                        + (cc ? bhnv.y : bhnv.x)));
                                yv[cc] = (1.0f - z) * n + z * (cc ? hv.y : hv.x);
                            }
                            *(float2*)(out + base) = make_float2(yv[0], yv[1]);
                            *(float2*)(out + TBH + base) = hv;   // hid copy
                        }
                    }
                }
            }
        }

        // both warps done reading buf -> producer may overwrite it
        BARW(barid);
        if (wm == 0) {
            if (t + 2 < WSTEPS) {
                const int t2 = t + 2;
                const uint4* src =
                    (const uint4*)(g_wscr + ((size_t)t2 * 4 + wh) * SLICE2);
                uint32_t dst = my_ws_sa + (uint32_t)buf * (SLICE2 * 4);
                #pragma unroll
                for (int i = 0; i < 12; i++) {
                    int e = i * 32 + lane;
                    asm volatile("cp.async.ca.shared.global [%0], [%1], 16;"
                                 :: "r"(dst + e * 16), "l"(src + e) : "memory");
                }
            }
            // always commit (possibly empty) to keep wait_group accounting
            asm volatile("cp.async.commit_group;" ::: "memory");
        }
    }
}

// ---------------------------------------------------------------------------
extern "C" void kernel_launch(void* const* d_in, const int* in_sizes, int n_in,
                              void* d_out, int out_size) {
    (void)in_sizes; (void)n_in; (void)out_size;
    const float* x    = (const float*)d_in[0];
    const float* hid  = (const float*)d_in[1];
    const float* W_ih = (const float*)d_in[2];
    const float* W_hh = (const float*)d_in[3];
    const float* b_ih = (const float*)d_in[4];
    const float* b_hh = (const float*)d_in[5];
    float* out = (float*)d_out;

    gru_prep_w<<<98304 / 256, 256>>>(W_ih, W_hh, b_ih, b_hh);

    const int smem_bytes =
        (2 * BM * 128 + 4 * 2 * SLICE2) * (int)sizeof(float);   // 112 KB
    cudaFuncSetAttribute(gru_main,
                         cudaFuncAttributeMaxDynamicSharedMemorySize, smem_bytes);
    gru_main<<<M_ / BM, NTHREADS, smem_bytes>>>(x, hid, out);
}

// round 15
// speedup vs baseline: 3.4376x; 1.6025x over previous
#include <cuda_runtime.h>
#include <cuda_fp16.h>
#include <cstdint>

// ============================================================================
// GRU per-timestep cell, batched: M = T*B = 131072, K = 128, H = 128.
//   r = sig(s_r + br), z = sig(s_z + bz), n = tanh(gi_n + bin + r*(gh_n + bhn))
//   y = (1-z)*n + z*hid ; out = concat(y, hid)
//
// R14: fp16 mma.sync m16n8k16 (same 10-bit mantissa as tf32, 2x rate, 2x K
// per instruction). Producer/consumer weight pipeline with named-barrier
// handoff (R10 structure). A-tiles in fp16 fragment-pair layout with chunk
// rotation (conflict-free LDS.64). fp32 accumulate + exact-fp32 hid in
// epilogue. BM=64, 256 thr, 2 CTAs/SM, smem 80KB.
// ============================================================================

#define T_ 512
#define B_ 256
#define H_ 128
#define K_ 128
#define M_ (T_ * B_)            // 131072
#define BM 64
#define NTHREADS 256
#define SLICE2 1536             // words per (step, wh): 2 kc16 * 6 mats * 16h * 16k fp16
#define WSTEPS 8                // 2 hblk * 4 kc16-pairs

// weight scratch: [step t][wh][kcsub][j][hh][c][p]  (half2 words)
__device__ uint32_t g_wscr[WSTEPS * 4 * SLICE2];   // 49152 words = 192 KB
// combined biases: [which][h]  which: 0=b_r, 1=b_z, 2=b_in, 3=b_hn
__device__ float g_bias[4 * H_];

__device__ __forceinline__ uint32_t packh2(float lo, float hi) {
    __half2 h = __floats2half2_rn(lo, hi);
    return *(uint32_t*)&h;
}

__device__ __forceinline__ void mma_f16(float* c, const uint32_t* a, const uint32_t* b) {
    asm volatile(
        "mma.sync.aligned.m16n8k16.row.col.f32.f16.f16.f32 "
        "{%0,%1,%2,%3}, {%4,%5,%6,%7}, {%8,%9}, {%0,%1,%2,%3};"
        : "+f"(c[0]), "+f"(c[1]), "+f"(c[2]), "+f"(c[3])
        : "r"(a[0]), "r"(a[1]), "r"(a[2]), "r"(a[3]),
          "r"(b[0]), "r"(b[1]));
}

__device__ __forceinline__ uint32_t smem_u32(const void* p) {
    uint32_t a;
    asm("{ .reg .u64 t; cvta.to.shared.u64 t, %1; cvt.u32.u64 %0, t; }"
        : "=r"(a) : "l"(p));
    return a;
}

#define BARW(id) asm volatile("bar.sync %0, 64;" :: "r"(id) : "memory")

__device__ __forceinline__ float sigmoidf_(float x) {
    return 1.0f / (1.0f + __expf(-x));
}
__device__ __forceinline__ float tanhf_(float x) {
    float e = __expf(2.0f * x);          // saturates correctly at +-inf
    return 1.0f - 2.0f / (e + 1.0f);
}

// A tile (fp16): row r has 64 half2 words. Chunk kk (k16 group) rotated by row:
//   word offset = r*64 + ((kk + r) & 7)*8 + c*2 + p
//   p=0 word: k = {2c, 2c+1};  p=1 word: k = {2c+8, 2c+9}   (k within chunk)
// LDS.64 at (.. + c*2) returns {a_lo, a_hi} for one row. Conflict-free per
// half-warp phase: bank = ((kk+r)&3)*8 + c*2, distinct for g=0..3 x c=0..3.
__device__ __forceinline__ int atile_off(int r, int kk, int c) {
    return r * 64 + (((kk + r) & 7) << 3) + (c << 1);
}

// ---------------------------------------------------------------------------
// Prep: scatter W_ih/W_hh into fp16 step-sliced fragment layout + biases.
//   within = idx % 768: p=w&1, c=(w>>1)&3, hh=(w>>3)&15, j=w>>7
//   blk = idx / 768:  kcsub=b&1, wh=(b>>1)&3, t=b>>3
//   kc16 = (t&3)*2 + kcsub, hblk = t>>2
//   word = half2( W[row][k0], W[row][k0+1] ),  k0 = kc16*16 + 2c + (p?8:0)
//   row  = (j%3)*128 + hblk*64 + wh*16 + hh
// ---------------------------------------------------------------------------
__global__ void gru_prep_w(const float* __restrict__ W_ih,
                           const float* __restrict__ W_hh,
                           const float* __restrict__ b_ih,
                           const float* __restrict__ b_hh) {
    int idx = blockIdx.x * 256 + threadIdx.x;        // 0..49151
    int within = idx % 768;
    int blk    = idx / 768;
    int p   = within & 1;
    int c   = (within >> 1) & 3;
    int hh  = (within >> 3) & 15;
    int j   = within >> 7;                           // 0..5
    int kcsub = blk & 1;
    int wh    = (blk >> 1) & 3;
    int t     = blk >> 3;                            // 0..7
    int hblk  = t >> 2;
    int kc16  = (t & 3) * 2 + kcsub;
    int row = (j % 3) * H_ + hblk * 64 + wh * 16 + hh;
    int k0 = kc16 * 16 + 2 * c + (p ? 8 : 0);
    const float* W = (j < 3) ? W_ih : W_hh;
    g_wscr[idx] = packh2(W[row * K_ + k0], W[row * K_ + k0 + 1]);

    if (idx < 4 * H_) {
        int which = idx >> 7, h = idx & 127;
        float v;
        if      (which == 0) v = b_ih[h]          + b_hh[h];
        else if (which == 1) v = b_ih[H_ + h]     + b_hh[H_ + h];
        else if (which == 2) v = b_ih[2 * H_ + h];
        else                 v = b_hh[2 * H_ + h];
        g_bias[idx] = v;
    }
}

// ---------------------------------------------------------------------------
// Main fused kernel: producer/consumer weight pipeline, fp16 MMA, 2 CTAs/SM.
// ---------------------------------------------------------------------------
__global__ void __launch_bounds__(NTHREADS, 2)
gru_main(const float* __restrict__ x,
         const float* __restrict__ hid,
         float* __restrict__ out)
{
    extern __shared__ char smem[];
    uint32_t* xs = (uint32_t*)smem;                  // [64][64] half2 words
    uint32_t* hs = xs + BM * 64;
    uint32_t* ws = hs + BM * 64;                     // [4 wh][2 buf][1536]

    const int tid  = threadIdx.x;
    const int warp = tid >> 5;
    const int lane = tid & 31;
    const int wm   = warp & 1;        // 0..1: 32-row slab; wm==0 is producer
    const int wh   = warp >> 1;       // 0..3: 16-col slab
    const int g    = lane >> 2;       // 0..7
    const int c    = lane & 3;        // 0..3
    const int bm   = blockIdx.x * BM;
    const int barid = 1 + wh;         // named barrier per warp pair

    const uint32_t my_ws_sa = smem_u32(ws) + (uint32_t)wh * (2 * SLICE2 * 4);
    const uint32_t* my_ws   = ws + wh * (2 * SLICE2);

    // ---- producer prologue: steps 0,1 ------------------------------------
    if (wm == 0) {
        #pragma unroll
        for (int t = 0; t < 2; t++) {
            const uint4* src = (const uint4*)(g_wscr + ((size_t)t * 4 + wh) * SLICE2);
            uint32_t dst = my_ws_sa + (uint32_t)t * (SLICE2 * 4);
            #pragma unroll
            for (int i = 0; i < 12; i++) {           // 384 uint4 / 32 lanes
                int e = i * 32 + lane;
                asm volatile("cp.async.ca.shared.global [%0], [%1], 16;"
                             :: "r"(dst + e * 16), "l"(src + e) : "memory");
            }
            asm volatile("cp.async.commit_group;" ::: "memory");
        }
    }

    // ---- load + convert x/hid tiles [64 x 128] -> fp16 pair layout -------
    {
        const float4* xg = (const float4*)(x   + (size_t)bm * K_);
        const float4* hg = (const float4*)(hid + (size_t)bm * K_);
        #pragma unroll
        for (int i = 0; i < 8; i++) {
            int idx  = i * NTHREADS + tid;       // 0..2047
            int row  = idx >> 5;
            int q    = idx & 31;                 // float4 index within row
            float4 vx = xg[row * 32 + q];
            float4 vh = hg[row * 32 + q];
            int kk = q >> 2, qq = q & 3;
            int base = row * 64 + (((kk + row) & 7) << 3);
            // word w'=2qq holds k {4qq,4qq+1}; w'=2qq+1 holds {4qq+2,4qq+3}
            // offset o(w') = w'<4 ? 2w' : 2w'-7
            int o1 = (qq < 2) ? 4 * qq : 4 * qq - 7;
            int o2 = (qq < 2) ? 4 * qq + 2 : 4 * qq - 5;
            xs[base + o1] = packh2(vx.x, vx.y);
            xs[base + o2] = packh2(vx.z, vx.w);
            hs[base + o1] = packh2(vh.x, vh.y);
            hs[base + o2] = packh2(vh.z, vh.w);
        }
    }
    __syncthreads();     // the ONLY block-wide barrier

    // ---- A fragment pipeline: load chunk kk=0 ----------------------------
    const int r0a = wm * 32 + g;          // mt=0 rows (g, g+8)
    const int r0b = wm * 32 + 16 + g;     // mt=1 rows
    uint32_t ax[2][4], ah[2][4];
    {
        uint2 lo, hi;
        lo = *(const uint2*)(xs + atile_off(r0a,     0, c));
        hi = *(const uint2*)(xs + atile_off(r0a + 8, 0, c));
        ax[0][0]=lo.x; ax[0][1]=hi.x; ax[0][2]=lo.y; ax[0][3]=hi.y;
        lo = *(const uint2*)(xs + atile_off(r0b,     0, c));
        hi = *(const uint2*)(xs + atile_off(r0b + 8, 0, c));
        ax[1][0]=lo.x; ax[1][1]=hi.x; ax[1][2]=lo.y; ax[1][3]=hi.y;
        lo = *(const uint2*)(hs + atile_off(r0a,     0, c));
        hi = *(const uint2*)(hs + atile_off(r0a + 8, 0, c));
        ah[0][0]=lo.x; ah[0][1]=hi.x; ah[0][2]=lo.y; ah[0][3]=hi.y;
        lo = *(const uint2*)(hs + atile_off(r0b,     0, c));
        hi = *(const uint2*)(hs + atile_off(r0b + 8, 0, c));
        ah[1][0]=lo.x; ah[1][1]=hi.x; ah[1][2]=lo.y; ah[1][3]=hi.y;
    }

    float acc[4][2][2][4];     // [gate][mt][nt][e]
    const size_t TBH = (size_t)M_ * H_;

    for (int t = 0; t < WSTEPS; t++) {
        const int buf  = t & 1;
        const int hblk = t >> 2;

        if (wm == 0)
            asm volatile("cp.async.wait_group 1;" ::: "memory");
        BARW(barid);

        #pragma unroll
        for (int kcsub = 0; kcsub < 2; kcsub++) {
            const int kc16 = (t & 3) * 2 + kcsub;

            if (kc16 == 0) {
                #pragma unroll
                for (int gt = 0; gt < 4; gt++)
                    #pragma unroll
                    for (int mt = 0; mt < 2; mt++)
                        #pragma unroll
                        for (int nt = 0; nt < 2; nt++)
                            #pragma unroll
                            for (int e = 0; e < 4; e++) acc[gt][mt][nt][e] = 0.f;
            }

            // ---- prefetch A fragments for next chunk ---------------------
            uint32_t axn[2][4], ahn[2][4];
            {
                const int kn = (kc16 + 1) & 7;
                uint2 lo, hi;
                lo = *(const uint2*)(xs + atile_off(r0a,     kn, c));
                hi = *(const uint2*)(xs + atile_off(r0a + 8, kn, c));
                axn[0][0]=lo.x; axn[0][1]=hi.x; axn[0][2]=lo.y; axn[0][3]=hi.y;
                lo = *(const uint2*)(xs + atile_off(r0b,     kn, c));
                hi = *(const uint2*)(xs + atile_off(r0b + 8, kn, c));
                axn[1][0]=lo.x; axn[1][1]=hi.x; axn[1][2]=lo.y; axn[1][3]=hi.y;
                lo = *(const uint2*)(hs + atile_off(r0a,     kn, c));
                hi = *(const uint2*)(hs + atile_off(r0a + 8, kn, c));
                ahn[0][0]=lo.x; ahn[0][1]=hi.x; ahn[0][2]=lo.y; ahn[0][3]=hi.y;
                lo = *(const uint2*)(hs + atile_off(r0b,     kn, c));
                hi = *(const uint2*)(hs + atile_off(r0b + 8, kn, c));
                ahn[1][0]=lo.x; ahn[1][1]=hi.x; ahn[1][2]=lo.y; ahn[1][3]=hi.y;
            }

            // ---- 24 MMAs over k16 ---------------------------------------
            const uint32_t* wb = my_ws + buf * SLICE2 + kcsub * 768;
            #pragma unroll
            for (int j = 0; j < 6; j++) {
                const int gate = (j == 0 || j == 3) ? 0 : (j == 1 || j == 4) ? 1
                               : (j == 2) ? 2 : 3;
                const uint32_t (*A)[4] = (j < 3) ? ax : ah;
                const uint32_t* wj = wb + j * 128;
                #pragma unroll
                for (int nt = 0; nt < 2; nt++) {
                    uint2 bb = *(const uint2*)(wj + ((nt * 8 + g) << 3) + (c << 1));
                    uint32_t bfrag[2] = {bb.x, bb.y};
                    mma_f16(acc[gate][0][nt], A[0], bfrag);
                    mma_f16(acc[gate][1][nt], A[1], bfrag);
                }
            }

            // rotate A pipeline
            #pragma unroll
            for (int mt = 0; mt < 2; mt++)
                #pragma unroll
                for (int e = 0; e < 4; e++) {
                    ax[mt][e] = axn[mt][e];
                    ah[mt][e] = ahn[mt][e];
                }

            // ---- epilogue at the end of each h-half ----------------------
            if (kc16 == 7) {
                const int h0 = hblk * 64;
                #pragma unroll
                for (int nt = 0; nt < 2; nt++) {
                    int hg_ = h0 + wh * 16 + nt * 8 + 2 * c;   // global h (even)
                    float2 brv  = __ldg((const float2*)(g_bias + hg_));
                    float2 bzv  = __ldg((const float2*)(g_bias + H_ + hg_));
                    float2 binv = __ldg((const float2*)(g_bias + 2 * H_ + hg_));
                    float2 bhnv = __ldg((const float2*)(g_bias + 3 * H_ + hg_));
                    #pragma unroll
                    for (int mt = 0; mt < 2; mt++) {
                        #pragma unroll
                        for (int rr = 0; rr < 2; rr++) {
                            int m = bm + wm * 32 + mt * 16 + g + rr * 8;
                            size_t base = (size_t)m * H_ + hg_;
                            float2 hv = __ldg((const float2*)(hid + base));
                            float yv[2];
                            #pragma unroll
                            for (int cc = 0; cc < 2; cc++) {
                                int e = rr * 2 + cc;
                                float r = sigmoidf_(acc[0][mt][nt][e]
                                                    + (cc ? brv.y : brv.x));
                                float z = sigmoidf_(acc[1][mt][nt][e]
                                                    + (cc ? bzv.y : bzv.x));
                                float n = tanhf_(acc[2][mt][nt][e]
                                                 + (cc ? binv.y : binv.x)
                                                 + r * (acc[3][mt][nt][e]
                                                        + (cc ? bhnv.y : bhnv.x)));
                                yv[cc] = (1.0f - z) * n + z * (cc ? hv.y : hv.x);
                            }
                            *(float2*)(out + base) = make_float2(yv[0], yv[1]);
                            *(float2*)(out + TBH + base) = hv;   // hid copy
                        }
                    }
                }
            }
        }

        // both warps done reading buf -> producer may overwrite it
        BARW(barid);
        if (wm == 0) {
            if (t + 2 < WSTEPS) {
                const int t2 = t + 2;
                const uint4* src =
                    (const uint4*)(g_wscr + ((size_t)t2 * 4 + wh) * SLICE2);
                uint32_t dst = my_ws_sa + (uint32_t)buf * (SLICE2 * 4);
                #pragma unroll
                for (int i = 0; i < 12; i++) {
                    int e = i * 32 + lane;
                    asm volatile("cp.async.ca.shared.global [%0], [%1], 16;"
                                 :: "r"(dst + e * 16), "l"(src + e) : "memory");
                }
            }
            asm volatile("cp.async.commit_group;" ::: "memory");
        }
    }
}

// ---------------------------------------------------------------------------
extern "C" void kernel_launch(void* const* d_in, const int* in_sizes, int n_in,
                              void* d_out, int out_size) {
    (void)in_sizes; (void)n_in; (void)out_size;
    const float* x    = (const float*)d_in[0];
    const float* hid  = (const float*)d_in[1];
    const float* W_ih = (const float*)d_in[2];
    const float* W_hh = (const float*)d_in[3];
    const float* b_ih = (const float*)d_in[4];
    const float* b_hh = (const float*)d_in[5];
    float* out = (float*)d_out;

    gru_prep_w<<<49152 / 256, 256>>>(W_ih, W_hh, b_ih, b_hh);

    const int smem_bytes =
        (2 * BM * 64 + 4 * 2 * SLICE2) * (int)sizeof(uint32_t);   // 80 KB
    cudaFuncSetAttribute(gru_main,
                         cudaFuncAttributeMaxDynamicSharedMemorySize, smem_bytes);
    gru_main<<<M_ / BM, NTHREADS, smem_bytes>>>(x, hid, out);
}

// round 16
// speedup vs baseline: 3.4920x; 1.0158x over previous
#include <cuda_runtime.h>
#include <cuda_fp16.h>
#include <cstdint>

// ============================================================================
// GRU per-timestep cell, batched: M = T*B = 131072, K = 128, H = 128.
//   r = sig(s_r + br), z = sig(s_z + bz), n = tanh(gi_n + bin + r*(gh_n + bhn))
//   y = (1-z)*n + z*hid ; out = concat(y, hid)
//
// R16: fp16 m16n8k16 (R14 base) + fully unrolled mainloop (all smem offsets
// immediate, no A-rotate MOVs, minimal address ALU) + B fragments via one
// LDS.128 per (j, nt-pair) (weight layout groups the 4 fragment words).
// Producer/consumer weight pipeline with named-barrier handoff.
// BM=64, 256 thr, 2 CTAs/SM, smem 80KB.
// ============================================================================

#define T_ 512
#define B_ 256
#define H_ 128
#define K_ 128
#define M_ (T_ * B_)            // 131072
#define BM 64
#define NTHREADS 256
#define SLICE2 1536             // words per (step, wh)
#define WSTEPS 8                // 2 hblk * 4 kc16-pairs

// weight scratch: [t][wh][kcsub*6+j][g][c][w]  (half2 words)
//   w: 0=(nt0,p0) 1=(nt0,p1) 2=(nt1,p0) 3=(nt1,p1)
__device__ uint32_t g_wscr[WSTEPS * 4 * SLICE2];   // 49152 words = 192 KB
// combined biases: [which][h]  which: 0=b_r, 1=b_z, 2=b_in, 3=b_hn
__device__ float g_bias[4 * H_];

__device__ __forceinline__ uint32_t packh2(float lo, float hi) {
    __half2 h = __floats2half2_rn(lo, hi);
    return *(uint32_t*)&h;
}

__device__ __forceinline__ void mma_f16(float* c, const uint32_t* a, const uint32_t* b) {
    asm volatile(
        "mma.sync.aligned.m16n8k16.row.col.f32.f16.f16.f32 "
        "{%0,%1,%2,%3}, {%4,%5,%6,%7}, {%8,%9}, {%0,%1,%2,%3};"
        : "+f"(c[0]), "+f"(c[1]), "+f"(c[2]), "+f"(c[3])
        : "r"(a[0]), "r"(a[1]), "r"(a[2]), "r"(a[3]),
          "r"(b[0]), "r"(b[1]));
}

__device__ __forceinline__ uint32_t smem_u32(const void* p) {
    uint32_t a;
    asm("{ .reg .u64 t; cvta.to.shared.u64 t, %1; cvt.u32.u64 %0, t; }"
        : "=r"(a) : "l"(p));
    return a;
}

#define BARW(id) asm volatile("bar.sync %0, 64;" :: "r"(id) : "memory")

__device__ __forceinline__ float sigmoidf_(float x) {
    return 1.0f / (1.0f + __expf(-x));
}
__device__ __forceinline__ float tanhf_(float x) {
    float e = __expf(2.0f * x);          // saturates correctly at +-inf
    return 1.0f - 2.0f / (e + 1.0f);
}

// ---------------------------------------------------------------------------
// Prep: scatter W_ih/W_hh into fp16 LDS.128-friendly fragment layout + biases.
//   idx = ((t*4 + wh)*12 + kcsub*6 + j)*128 + g*16 + c*4 + w
//   nt = w>>1, p = w&1; kc16 = (t&3)*2 + kcsub; hblk = t>>2
//   row = (j%3)*128 + hblk*64 + wh*16 + nt*8 + g; k0 = kc16*16 + 2c + 8p
//   word = half2( W[row][k0], W[row][k0+1] )
// ---------------------------------------------------------------------------
__global__ void gru_prep_w(const float* __restrict__ W_ih,
                           const float* __restrict__ W_hh,
                           const float* __restrict__ b_ih,
                           const float* __restrict__ b_hh) {
    int idx = blockIdx.x * 256 + threadIdx.x;        // 0..49151
    int w   = idx & 3;
    int c   = (idx >> 2) & 3;
    int g   = (idx >> 4) & 7;
    int jb  = (idx >> 7) % 12;                       // kcsub*6 + j
    int blk = idx / 1536;                            // t*4 + wh
    int kcsub = jb / 6;
    int j     = jb % 6;
    int wh  = blk & 3;
    int t   = blk >> 2;                              // 0..7
    int hblk = t >> 2;
    int kc16 = (t & 3) * 2 + kcsub;
    int nt = w >> 1, p = w & 1;
    int row = (j % 3) * H_ + hblk * 64 + wh * 16 + nt * 8 + g;
    int k0 = kc16 * 16 + 2 * c + 8 * p;
    const float* W = (j < 3) ? W_ih : W_hh;
    g_wscr[idx] = packh2(W[row * K_ + k0], W[row * K_ + k0 + 1]);

    if (idx < 4 * H_) {
        int which = idx >> 7, h = idx & 127;
        float v;
        if      (which == 0) v = b_ih[h]          + b_hh[h];
        else if (which == 1) v = b_ih[H_ + h]     + b_hh[H_ + h];
        else if (which == 2) v = b_ih[2 * H_ + h];
        else                 v = b_hh[2 * H_ + h];
        g_bias[idx] = v;
    }
}

// ---------------------------------------------------------------------------
// Main fused kernel: fully unrolled, producer/consumer pipeline, 2 CTAs/SM.
// ---------------------------------------------------------------------------
__global__ void __launch_bounds__(NTHREADS, 2)
gru_main(const float* __restrict__ x,
         const float* __restrict__ hid,
         float* __restrict__ out)
{
    extern __shared__ char smem[];
    uint32_t* xs = (uint32_t*)smem;                  // [64][64] half2 words
    uint32_t* hs = xs + BM * 64;                     // +4096 words
    uint32_t* ws = hs + BM * 64;                     // [4 wh][2 buf][1536]

    const int tid  = threadIdx.x;
    const int warp = tid >> 5;
    const int lane = tid & 31;
    const int wm   = warp & 1;        // 0..1: 32-row slab; wm==0 is producer
    const int wh   = warp >> 1;       // 0..3: 16-col slab
    const int g    = lane >> 2;       // 0..7
    const int c    = lane & 3;        // 0..3
    const int bm   = blockIdx.x * BM;
    const int barid = 1 + wh;         // named barrier per warp pair

    const uint32_t my_ws_sa = smem_u32(ws) + (uint32_t)wh * (2 * SLICE2 * 4);

    // ---- producer prologue: steps 0,1 ------------------------------------
    if (wm == 0) {
        #pragma unroll
        for (int t = 0; t < 2; t++) {
            const uint4* src = (const uint4*)(g_wscr + ((size_t)t * 4 + wh) * SLICE2);
            uint32_t dst = my_ws_sa + (uint32_t)t * (SLICE2 * 4);
            #pragma unroll
            for (int i = 0; i < 12; i++) {           // 384 uint4 / 32 lanes
                int e = i * 32 + lane;
                asm volatile("cp.async.ca.shared.global [%0], [%1], 16;"
                             :: "r"(dst + e * 16), "l"(src + e) : "memory");
            }
            asm volatile("cp.async.commit_group;" ::: "memory");
        }
    }

    // ---- load + convert x/hid tiles [64 x 128] -> fp16 rotated layout ----
    // A tile word (r, kk, c, p) at r*64 + ((kk + r)&7)*8 + c*2 + p
    {
        const float4* xg = (const float4*)(x   + (size_t)bm * K_);
        const float4* hg = (const float4*)(hid + (size_t)bm * K_);
        #pragma unroll
        for (int i = 0; i < 8; i++) {
            int idx  = i * NTHREADS + tid;       // 0..2047
            int row  = idx >> 5;
            int q    = idx & 31;                 // float4 index within row
            float4 vx = xg[row * 32 + q];
            float4 vh = hg[row * 32 + q];
            int kk = q >> 2, qq = q & 3;
            int base = row * 64 + (((kk + row) & 7) << 3);
            int o1 = (qq < 2) ? 4 * qq : 4 * qq - 7;
            int o2 = (qq < 2) ? 4 * qq + 2 : 4 * qq - 5;
            xs[base + o1] = packh2(vx.x, vx.y);
            xs[base + o2] = packh2(vx.z, vx.w);
            hs[base + o1] = packh2(vh.x, vh.y);
            hs[base + o2] = packh2(vh.z, vh.w);
        }
    }
    __syncthreads();     // the ONLY block-wide barrier

    // ---- precomputed pointers --------------------------------------------
    const int r0a = wm * 32 + g;                 // rows r0a, +8, +16, +24
    const int rot = r0a & 7;                     // same rotation for all 4 rows
    const uint32_t* pxa = xs + r0a * 64 + c * 2; // x row r0a (hs = +4096 words)
    const uint32_t* pB  = ws + wh * (2 * SLICE2) + g * 16 + c * 4;

    float acc[4][2][2][4];     // [gate][mt][nt][e]
    const size_t TBH = (size_t)M_ * H_;

    #pragma unroll
    for (int t = 0; t < WSTEPS; t++) {
        if (wm == 0)
            asm volatile("cp.async.wait_group 1;" ::: "memory");
        BARW(barid);

        #pragma unroll
        for (int kcsub = 0; kcsub < 2; kcsub++) {
            const int kc16 = (t & 3) * 2 + kcsub;

            if (kc16 == 0) {
                #pragma unroll
                for (int gt = 0; gt < 4; gt++)
                    #pragma unroll
                    for (int mt = 0; mt < 2; mt++)
                        #pragma unroll
                        for (int nt = 0; nt < 2; nt++)
                            #pragma unroll
                            for (int e = 0; e < 4; e++) acc[gt][mt][nt][e] = 0.f;
            }

            // ---- A fragments: 8 LDS.64, one shared rotation offset -------
            uint32_t ax[2][4], ah[2][4];
            {
                const uint32_t* pk = pxa + (((kc16 + rot) & 7) << 3);
                uint2 v;
                v = *(const uint2*)(pk +    0); ax[0][0]=v.x; ax[0][2]=v.y;
                v = *(const uint2*)(pk +  512); ax[0][1]=v.x; ax[0][3]=v.y;
                v = *(const uint2*)(pk + 1024); ax[1][0]=v.x; ax[1][2]=v.y;
                v = *(const uint2*)(pk + 1536); ax[1][1]=v.x; ax[1][3]=v.y;
                v = *(const uint2*)(pk + 4096); ah[0][0]=v.x; ah[0][2]=v.y;
                v = *(const uint2*)(pk + 4608); ah[0][1]=v.x; ah[0][3]=v.y;
                v = *(const uint2*)(pk + 5120); ah[1][0]=v.x; ah[1][2]=v.y;
                v = *(const uint2*)(pk + 5632); ah[1][1]=v.x; ah[1][3]=v.y;
            }

            // ---- 24 MMAs, B via 6 LDS.128 (all-immediate offsets) --------
            #pragma unroll
            for (int j = 0; j < 6; j++) {
                const int gate = (j == 0 || j == 3) ? 0 : (j == 1 || j == 4) ? 1
                               : (j == 2) ? 2 : 3;
                const uint32_t (*A)[4] = (j < 3) ? ax : ah;
                uint4 bb = *(const uint4*)(pB + (t & 1) * SLICE2
                                              + kcsub * 768 + j * 128);
                uint32_t b0[2] = {bb.x, bb.y};
                uint32_t b1[2] = {bb.z, bb.w};
                mma_f16(acc[gate][0][0], A[0], b0);
                mma_f16(acc[gate][1][0], A[1], b0);
                mma_f16(acc[gate][0][1], A[0], b1);
                mma_f16(acc[gate][1][1], A[1], b1);
            }

            // ---- epilogue at the end of each h-half ----------------------
            if (kc16 == 7) {
                const int hblk = t >> 2;
                const int h0 = hblk * 64;
                #pragma unroll
                for (int nt = 0; nt < 2; nt++) {
                    int hg_ = h0 + wh * 16 + nt * 8 + 2 * c;   // global h (even)
                    float2 brv  = __ldg((const float2*)(g_bias + hg_));
                    float2 bzv  = __ldg((const float2*)(g_bias + H_ + hg_));
                    float2 binv = __ldg((const float2*)(g_bias + 2 * H_ + hg_));
                    float2 bhnv = __ldg((const float2*)(g_bias + 3 * H_ + hg_));
                    #pragma unroll
                    for (int mt = 0; mt < 2; mt++) {
                        #pragma unroll
                        for (int rr = 0; rr < 2; rr++) {
                            int m = bm + wm * 32 + mt * 16 + g + rr * 8;
                            size_t base = (size_t)m * H_ + hg_;
                            float2 hv = __ldg((const float2*)(hid + base));
                            float yv[2];
                            #pragma unroll
                            for (int cc = 0; cc < 2; cc++) {
                                int e = rr * 2 + cc;
                                float r = sigmoidf_(acc[0][mt][nt][e]
                                                    + (cc ? brv.y : brv.x));
                                float z = sigmoidf_(acc[1][mt][nt][e]
                                                    + (cc ? bzv.y : bzv.x));
                                float n = tanhf_(acc[2][mt][nt][e]
                                                 + (cc ? binv.y : binv.x)
                                                 + r * (acc[3][mt][nt][e]
                                                        + (cc ? bhnv.y : bhnv.x)));
                                yv[cc] = (1.0f - z) * n + z * (cc ? hv.y : hv.x);
                            }
                            *(float2*)(out + base) = make_float2(yv[0], yv[1]);
                            *(float2*)(out + TBH + base) = hv;   // hid copy
                        }
                    }
                }
            }
        }

        // both warps done reading buf (t&1) -> producer may overwrite it
        BARW(barid);
        if (wm == 0) {
            if (t + 2 < WSTEPS) {
                const uint4* src =
                    (const uint4*)(g_wscr + ((size_t)(t + 2) * 4 + wh) * SLICE2);
                uint32_t dst = my_ws_sa + (uint32_t)(t & 1) * (SLICE2 * 4);
                #pragma unroll
                for (int i = 0; i < 12; i++) {
                    int e = i * 32 + lane;
                    asm volatile("cp.async.ca.shared.global [%0], [%1], 16;"
                                 :: "r"(dst + e * 16), "l"(src + e) : "memory");
                }
            }
            asm volatile("cp.async.commit_group;" ::: "memory");
        }
    }
}

// ---------------------------------------------------------------------------
extern "C" void kernel_launch(void* const* d_in, const int* in_sizes, int n_in,
                              void* d_out, int out_size) {
    (void)in_sizes; (void)n_in; (void)out_size;
    const float* x    = (const float*)d_in[0];
    const float* hid  = (const float*)d_in[1];
    const float* W_ih = (const float*)d_in[2];
    const float* W_hh = (const float*)d_in[3];
    const float* b_ih = (const float*)d_in[4];
    const float* b_hh = (const float*)d_in[5];
    float* out = (float*)d_out;

    gru_prep_w<<<49152 / 256, 256>>>(W_ih, W_hh, b_ih, b_hh);

    const int smem_bytes =
        (2 * BM * 64 + 4 * 2 * SLICE2) * (int)sizeof(uint32_t);   // 80 KB
    cudaFuncSetAttribute(gru_main,
                         cudaFuncAttributeMaxDynamicSharedMemorySize, smem_bytes);
    gru_main<<<M_ / BM, NTHREADS, smem_bytes>>>(x, hid, out);
}

// round 17
// speedup vs baseline: 3.6199x; 1.0366x over previous
#include <cuda_runtime.h>
#include <cuda_fp16.h>
#include <cstdint>

// ============================================================================
// GRU per-timestep cell, batched: M = T*B = 131072, K = 128, H = 128.
//   r = sig(s_r + br), z = sig(s_z + bz), n = tanh(gi_n + bin + r*(gh_n + bhn))
//   y = (1-z)*n + z*hid ; out = concat(y, hid)
//
// R17 (on R16 base): fp16 m16n8k16, fully unrolled, producer/consumer weight
// pipeline with named-barrier handoff.  New:
//  - tanh.approx.f32 gate math (sigmoid via tanh identity, biases pre-halved)
//  - fp32 hid tile in smem: epilogue LDS instead of LDG; exact hid copy
//  - interleaved x/h fp16 tile: A fragments via 4 LDS.128 (was 8 LDS.64)
// BM=64, 256 thr, 2 CTAs/SM, smem 112KB.
// ============================================================================

#define T_ 512
#define B_ 256
#define H_ 128
#define K_ 128
#define M_ (T_ * B_)            // 131072
#define BM 64
#define NTHREADS 256
#define SLICE2 1536             // words per (step, wh)
#define WSTEPS 8                // 2 hblk * 4 kc16-pairs

// weight scratch: [t][wh][kcsub*6+j][g][c][w]  (half2 words)
//   w: 0=(nt0,p0) 1=(nt0,p1) 2=(nt1,p0) 3=(nt1,p1)
__device__ uint32_t g_wscr[WSTEPS * 4 * SLICE2];   // 49152 words = 192 KB
// biases: [0]=0.5*(br_ih+br_hh)  [1]=0.5*(bz_ih+bz_hh)  [2]=bin  [3]=bhn
__device__ float g_bias[4 * H_];

__device__ __forceinline__ uint32_t packh2(float lo, float hi) {
    __half2 h = __floats2half2_rn(lo, hi);
    return *(uint32_t*)&h;
}

__device__ __forceinline__ void mma_f16(float* c, const uint32_t* a, const uint32_t* b) {
    asm volatile(
        "mma.sync.aligned.m16n8k16.row.col.f32.f16.f16.f32 "
        "{%0,%1,%2,%3}, {%4,%5,%6,%7}, {%8,%9}, {%0,%1,%2,%3};"
        : "+f"(c[0]), "+f"(c[1]), "+f"(c[2]), "+f"(c[3])
        : "r"(a[0]), "r"(a[1]), "r"(a[2]), "r"(a[3]),
          "r"(b[0]), "r"(b[1]));
}

__device__ __forceinline__ uint32_t smem_u32(const void* p) {
    uint32_t a;
    asm("{ .reg .u64 t; cvta.to.shared.u64 t, %1; cvt.u32.u64 %0, t; }"
        : "=r"(a) : "l"(p));
    return a;
}

#define BARW(id) asm volatile("bar.sync %0, 64;" :: "r"(id) : "memory")

__device__ __forceinline__ float tanh_ap(float x) {
    float y;
    asm("tanh.approx.f32 %0, %1;" : "=f"(y) : "f"(x));
    return y;
}

// ---------------------------------------------------------------------------
// Prep: scatter W_ih/W_hh into fp16 LDS.128-friendly fragment layout + biases.
//   idx = ((t*4 + wh)*12 + kcsub*6 + j)*128 + g*16 + c*4 + w
//   nt = w>>1, p = w&1; kc16 = (t&3)*2 + kcsub; hblk = t>>2
//   row = (j%3)*128 + hblk*64 + wh*16 + nt*8 + g; k0 = kc16*16 + 2c + 8p
// ---------------------------------------------------------------------------
__global__ void gru_prep_w(const float* __restrict__ W_ih,
                           const float* __restrict__ W_hh,
                           const float* __restrict__ b_ih,
                           const float* __restrict__ b_hh) {
    int idx = blockIdx.x * 256 + threadIdx.x;        // 0..49151
    int w   = idx & 3;
    int c   = (idx >> 2) & 3;
    int g   = (idx >> 4) & 7;
    int jb  = (idx >> 7) % 12;                       // kcsub*6 + j
    int blk = idx / 1536;                            // t*4 + wh
    int kcsub = jb / 6;
    int j     = jb % 6;
    int wh  = blk & 3;
    int t   = blk >> 2;                              // 0..7
    int hblk = t >> 2;
    int kc16 = (t & 3) * 2 + kcsub;
    int nt = w >> 1, p = w & 1;
    int row = (j % 3) * H_ + hblk * 64 + wh * 16 + nt * 8 + g;
    int k0 = kc16 * 16 + 2 * c + 8 * p;
    const float* W = (j < 3) ? W_ih : W_hh;
    g_wscr[idx] = packh2(W[row * K_ + k0], W[row * K_ + k0 + 1]);

    if (idx < 4 * H_) {
        int which = idx >> 7, h = idx & 127;
        float v;
        if      (which == 0) v = 0.5f * (b_ih[h]      + b_hh[h]);
        else if (which == 1) v = 0.5f * (b_ih[H_ + h] + b_hh[H_ + h]);
        else if (which == 2) v = b_ih[2 * H_ + h];
        else                 v = b_hh[2 * H_ + h];
        g_bias[idx] = v;
    }
}

// ---------------------------------------------------------------------------
// Main fused kernel.
// smem: xh fp16 interleaved tile [64][128 words] (32KB)
//       ws  weight slices [4 wh][2 buf][1536]    (48KB)
//       hf  fp32 hid tile [64][128]              (32KB)       total 112KB
// xh word layout: (r, kk, c, w) at r*128 + ((kk + r)&7)*16 + c*4 + w
//   w: 0 = x_p0 (k{2c,2c+1}), 1 = x_p1 (k{2c+8,2c+9}), 2 = h_p0, 3 = h_p1
// ---------------------------------------------------------------------------
__global__ void __launch_bounds__(NTHREADS, 2)
gru_main(const float* __restrict__ x,
         const float* __restrict__ hid,
         float* __restrict__ out)
{
    extern __shared__ char smem[];
    uint32_t* xh = (uint32_t*)smem;                  // 8192 words
    uint32_t* ws = xh + BM * 128;                    // 12288 words
    float*    hf = (float*)(ws + 4 * 2 * SLICE2);    // 8192 words

    const int tid  = threadIdx.x;
    const int warp = tid >> 5;
    const int lane = tid & 31;
    const int wm   = warp & 1;        // 0..1: 32-row slab; wm==0 is producer
    const int wh   = warp >> 1;       // 0..3: 16-col slab
    const int g    = lane >> 2;       // 0..7
    const int c    = lane & 3;        // 0..3
    const int bm   = blockIdx.x * BM;
    const int barid = 1 + wh;         // named barrier per warp pair

    const uint32_t my_ws_sa = smem_u32(ws) + (uint32_t)wh * (2 * SLICE2 * 4);

    // ---- producer prologue: steps 0,1 ------------------------------------
    if (wm == 0) {
        #pragma unroll
        for (int t = 0; t < 2; t++) {
            const uint4* src = (const uint4*)(g_wscr + ((size_t)t * 4 + wh) * SLICE2);
            uint32_t dst = my_ws_sa + (uint32_t)t * (SLICE2 * 4);
            #pragma unroll
            for (int i = 0; i < 12; i++) {           // 384 uint4 / 32 lanes
                int e = i * 32 + lane;
                asm volatile("cp.async.ca.shared.global [%0], [%1], 16;"
                             :: "r"(dst + e * 16), "l"(src + e) : "memory");
            }
            asm volatile("cp.async.commit_group;" ::: "memory");
        }
    }

    // ---- load tiles: x,hid fp32 -> interleaved fp16 xh + fp32 hf ---------
    {
        const float4* xg = (const float4*)(x   + (size_t)bm * K_);
        const float4* hg = (const float4*)(hid + (size_t)bm * K_);
        #pragma unroll
        for (int i = 0; i < 8; i++) {
            int idx  = i * NTHREADS + tid;       // 0..2047
            int row  = idx >> 5;
            int q    = idx & 31;                 // float4 index within row
            float4 vx = xg[row * 32 + q];
            float4 vh = hg[row * 32 + q];
            int kk = q >> 2, qq = q & 3;
            int base = row * 128 + (((kk + row) & 7) << 4);
            // x word offsets within the 16-word chunk (w=0/1), h at +2
            int o1 = (qq < 2) ? 8 * qq      : 8 * qq - 15;  // (vx.x,vx.y)
            int o2 = (qq < 2) ? 8 * qq + 4  : 8 * qq - 11;  // (vx.z,vx.w)
            xh[base + o1]     = packh2(vx.x, vx.y);
            xh[base + o2]     = packh2(vx.z, vx.w);
            xh[base + o1 + 2] = packh2(vh.x, vh.y);
            xh[base + o2 + 2] = packh2(vh.z, vh.w);
            *(float4*)(hf + row * 128 + q * 4) = vh;        // exact fp32 copy
        }
    }
    __syncthreads();     // the ONLY block-wide barrier

    // ---- precomputed pointers --------------------------------------------
    const int r0a = wm * 32 + g;                 // rows r0a, +8, +16, +24 (same mod 8)
    const uint32_t* pA = xh + r0a * 128 + c * 4;
    const uint32_t* pB = ws + wh * (2 * SLICE2) + g * 16 + c * 4;

    float acc[4][2][2][4];     // [gate][mt][nt][e]
    const size_t TBH = (size_t)M_ * H_;

    #pragma unroll
    for (int t = 0; t < WSTEPS; t++) {
        if (wm == 0)
            asm volatile("cp.async.wait_group 1;" ::: "memory");
        BARW(barid);

        #pragma unroll
        for (int kcsub = 0; kcsub < 2; kcsub++) {
            const int kc16 = (t & 3) * 2 + kcsub;

            if (kc16 == 0) {
                #pragma unroll
                for (int gt = 0; gt < 4; gt++)
                    #pragma unroll
                    for (int mt = 0; mt < 2; mt++)
                        #pragma unroll
                        for (int nt = 0; nt < 2; nt++)
                            #pragma unroll
                            for (int e = 0; e < 4; e++) acc[gt][mt][nt][e] = 0.f;
            }

            // ---- A fragments: 4 LDS.128 (x and h words together) ---------
            uint32_t ax[2][4], ah[2][4];
            {
                const uint32_t* pk = pA + (((kc16 + g) & 7) << 4);
                uint4 v;
                v = *(const uint4*)(pk +    0);           // row r0a
                ax[0][0]=v.x; ax[0][2]=v.y; ah[0][0]=v.z; ah[0][2]=v.w;
                v = *(const uint4*)(pk + 1024);           // row r0a+8
                ax[0][1]=v.x; ax[0][3]=v.y; ah[0][1]=v.z; ah[0][3]=v.w;
                v = *(const uint4*)(pk + 2048);           // row r0a+16
                ax[1][0]=v.x; ax[1][2]=v.y; ah[1][0]=v.z; ah[1][2]=v.w;
                v = *(const uint4*)(pk + 3072);           // row r0a+24
                ax[1][1]=v.x; ax[1][3]=v.y; ah[1][1]=v.z; ah[1][3]=v.w;
            }

            // ---- 24 MMAs, B via 6 LDS.128 (all-immediate offsets) --------
            #pragma unroll
            for (int j = 0; j < 6; j++) {
                const int gate = (j == 0 || j == 3) ? 0 : (j == 1 || j == 4) ? 1
                               : (j == 2) ? 2 : 3;
                const uint32_t (*A)[4] = (j < 3) ? ax : ah;
                uint4 bb = *(const uint4*)(pB + (t & 1) * SLICE2
                                              + kcsub * 768 + j * 128);
                uint32_t b0[2] = {bb.x, bb.y};
                uint32_t b1[2] = {bb.z, bb.w};
                mma_f16(acc[gate][0][0], A[0], b0);
                mma_f16(acc[gate][1][0], A[1], b0);
                mma_f16(acc[gate][0][1], A[0], b1);
                mma_f16(acc[gate][1][1], A[1], b1);
            }

            // ---- epilogue at the end of each h-half ----------------------
            if (kc16 == 7) {
                const int hblk = t >> 2;
                const int h0 = hblk * 64;
                #pragma unroll
                for (int nt = 0; nt < 2; nt++) {
                    int hg_ = h0 + wh * 16 + nt * 8 + 2 * c;   // global h (even)
                    float2 brh  = __ldg((const float2*)(g_bias + hg_));          // halved
                    float2 bzh  = __ldg((const float2*)(g_bias + H_ + hg_));     // halved
                    float2 binv = __ldg((const float2*)(g_bias + 2 * H_ + hg_));
                    float2 bhnv = __ldg((const float2*)(g_bias + 3 * H_ + hg_));
                    #pragma unroll
                    for (int mt = 0; mt < 2; mt++) {
                        #pragma unroll
                        for (int rr = 0; rr < 2; rr++) {
                            int lrow = wm * 32 + mt * 16 + g + rr * 8;
                            int m = bm + lrow;
                            size_t base = (size_t)m * H_ + hg_;
                            float2 hv = *(const float2*)(hf + lrow * 128 + hg_);
                            float yv[2];
                            #pragma unroll
                            for (int cc = 0; cc < 2; cc++) {
                                int e = rr * 2 + cc;
                                float r = fmaf(tanh_ap(fmaf(acc[0][mt][nt][e], 0.5f,
                                                            cc ? brh.y : brh.x)),
                                               0.5f, 0.5f);
                                float z = fmaf(tanh_ap(fmaf(acc[1][mt][nt][e], 0.5f,
                                                            cc ? bzh.y : bzh.x)),
                                               0.5f, 0.5f);
                                float n = tanh_ap(acc[2][mt][nt][e]
                                                  + (cc ? binv.y : binv.x)
                                                  + r * (acc[3][mt][nt][e]
                                                         + (cc ? bhnv.y : bhnv.x)));
                                float h = cc ? hv.y : hv.x;
                                yv[cc] = n + z * (h - n);
                            }
                            *(float2*)(out + base) = make_float2(yv[0], yv[1]);
                            *(float2*)(out + TBH + base) = hv;   // exact hid copy
                        }
                    }
                }
            }
        }

        // both warps done reading buf (t&1) -> producer may overwrite it
        BARW(barid);
        if (wm == 0) {
            if (t + 2 < WSTEPS) {
                const uint4* src =
                    (const uint4*)(g_wscr + ((size_t)(t + 2) * 4 + wh) * SLICE2);
                uint32_t dst = my_ws_sa + (uint32_t)(t & 1) * (SLICE2 * 4);
                #pragma unroll
                for (int i = 0; i < 12; i++) {
                    int e = i * 32 + lane;
                    asm volatile("cp.async.ca.shared.global [%0], [%1], 16;"
                                 :: "r"(dst + e * 16), "l"(src + e) : "memory");
                }
            }
            asm volatile("cp.async.commit_group;" ::: "memory");
        }
    }
}

// ---------------------------------------------------------------------------
extern "C" void kernel_launch(void* const* d_in, const int* in_sizes, int n_in,
                              void* d_out, int out_size) {
    (void)in_sizes; (void)n_in; (void)out_size;
    const float* x    = (const float*)d_in[0];
    const float* hid  = (const float*)d_in[1];
    const float* W_ih = (const float*)d_in[2];
    const float* W_hh = (const float*)d_in[3];
    const float* b_ih = (const float*)d_in[4];
    const float* b_hh = (const float*)d_in[5];
    float* out = (float*)d_out;

    gru_prep_w<<<49152 / 256, 256>>>(W_ih, W_hh, b_ih, b_hh);

    const int smem_bytes =
        (BM * 128 + 4 * 2 * SLICE2 + BM * 128) * (int)sizeof(uint32_t);  // 112 KB
    cudaFuncSetAttribute(gru_main,
                         cudaFuncAttributeMaxDynamicSharedMemorySize, smem_bytes);
    gru_main<<<M_ / BM, NTHREADS, smem_bytes>>>(x, hid, out);
}